// round 1
// baseline (speedup 1.0000x reference)
#include <cuda_runtime.h>
#include <cuda_bf16.h>
#include <math.h>

#define B 64
#define L 256
#define H 1024
#define P 64
#define A 512
#define T 8
#define F (H + 2 * P)   // 1152

// ---------------- scratch (device globals; no allocation allowed) ----------
__device__ float g_ef[B * 4 * H];       // entity_features [B, 4H]
__device__ float g_dense_ent[B * A];    // [B, A]
__device__ float g_vu[B * L];           // [B, L]

// ---------------------------------------------------------------------------
// K1: gather entity hiddens, latent types, build entity_features.
// Also zeroes g_dense_ent and g_vu for this launch.
// grid = B blocks, 256 threads.
// ---------------------------------------------------------------------------
__global__ void k1_entity_prep(const float* __restrict__ wh,
                               const int* __restrict__ e1_end,
                               const int* __restrict__ e2_end,
                               const float* __restrict__ te) {
    const int b = blockIdx.x;
    const int tid = threadIdx.x;
    const int lane = tid & 31;
    const int wid = tid >> 5;

    __shared__ float wsum[8][16];
    __shared__ float scores[16];
    __shared__ float alpha[2][T];

    const float* h1 = wh + ((size_t)b * L + e1_end[b]) * H;
    const float* h2 = wh + ((size_t)b * L + e2_end[b]) * H;

    // 16 dot products of length H (8 for each entity)
    float s[16];
#pragma unroll
    for (int i = 0; i < 16; i++) s[i] = 0.f;
    for (int h = tid; h < H; h += 256) {
        float v1 = h1[h], v2 = h2[h];
#pragma unroll
        for (int t = 0; t < T; t++) {
            float c = te[t * H + h];
            s[t] += v1 * c;
            s[8 + t] += v2 * c;
        }
    }
#pragma unroll
    for (int off = 16; off; off >>= 1)
#pragma unroll
        for (int i = 0; i < 16; i++) s[i] += __shfl_xor_sync(0xffffffffu, s[i], off);
    if (lane == 0)
#pragma unroll
        for (int i = 0; i < 16; i++) wsum[wid][i] = s[i];
    __syncthreads();
    if (tid < 16) {
        float tot = 0.f;
#pragma unroll
        for (int w = 0; w < 8; w++) tot += wsum[w][tid];
        scores[tid] = tot;
    }
    __syncthreads();
    if (tid < 2) {
        const float* sc = scores + tid * 8;
        float m = -1e30f;
#pragma unroll
        for (int i = 0; i < T; i++) m = fmaxf(m, sc[i]);
        float sum = 0.f;
        float e[T];
#pragma unroll
        for (int i = 0; i < T; i++) { e[i] = expf(sc[i] - m); sum += e[i]; }
        float inv = 1.f / sum;
#pragma unroll
        for (int i = 0; i < T; i++) alpha[tid][i] = e[i] * inv;
    }
    __syncthreads();

    float* ef = g_ef + (size_t)b * 4 * H;
    for (int h = tid; h < H; h += 256) {
        float t1 = 0.f, t2 = 0.f;
#pragma unroll
        for (int t = 0; t < T; t++) {
            float c = te[t * H + h];
            t1 += alpha[0][t] * c;
            t2 += alpha[1][t] * c;
        }
        ef[h]         = h1[h];
        ef[H + h]     = t1;
        ef[2 * H + h] = h2[h];
        ef[3 * H + h] = t2;
    }

    // zero accumulators for this launch
    g_vu[b * L + tid] = 0.f;
    g_dense_ent[b * A + tid] = 0.f;
    g_dense_ent[b * A + 256 + tid] = 0.f;
}

// ---------------------------------------------------------------------------
// K2: dense_ent = ef[B,4H] @ W_ent[4H,A], split-K with atomic accumulate.
// grid = (A/64, 4H/512) = (8, 8); 256 threads; each thread 4x4 outputs.
// ---------------------------------------------------------------------------
__global__ void k2_dense_ent(const float* __restrict__ W_ent) {
    const int a0 = blockIdx.x * 64;
    const int k0 = blockIdx.y * 512;
    const int tid = threadIdx.x;
    const int tx = tid & 15;       // a group
    const int ty = tid >> 4;       // b group

    __shared__ float sE[16][65];   // [kt][b]
    __shared__ float sW[16][64];   // [kt][a]

    float acc[4][4];
#pragma unroll
    for (int r = 0; r < 4; r++)
#pragma unroll
        for (int c = 0; c < 4; c++) acc[r][c] = 0.f;

    for (int ks = 0; ks < 512; ks += 16) {
#pragma unroll
        for (int i = 0; i < 4; i++) {
            int idx = tid + i * 256;
            int kt = idx & 15, bb = idx >> 4;
            sE[kt][bb] = g_ef[(size_t)bb * (4 * H) + k0 + ks + kt];
        }
#pragma unroll
        for (int i = 0; i < 4; i++) {
            int idx = tid + i * 256;
            int an = idx & 63, kt = idx >> 6;
            sW[kt][an] = W_ent[(size_t)(k0 + ks + kt) * A + a0 + an];
        }
        __syncthreads();
#pragma unroll
        for (int kt = 0; kt < 16; kt++) {
            float e[4], w[4];
#pragma unroll
            for (int r = 0; r < 4; r++) e[r] = sE[kt][ty * 4 + r];
#pragma unroll
            for (int c = 0; c < 4; c++) w[c] = sW[kt][tx * 4 + c];
#pragma unroll
            for (int r = 0; r < 4; r++)
#pragma unroll
                for (int c = 0; c < 4; c++) acc[r][c] += e[r] * w[c];
        }
        __syncthreads();
    }
#pragma unroll
    for (int r = 0; r < 4; r++)
#pragma unroll
        for (int c = 0; c < 4; c++)
            atomicAdd(&g_dense_ent[(ty * 4 + r) * A + a0 + tx * 4 + c], acc[r][c]);
}

// ---------------------------------------------------------------------------
// K3: main fused GEMM + tanh + v-dot -> partial vu.
// dense_pos tile [64 l x 128 a], K=1152 over [wh | pe1 | pe2] @ W_pos.
// grid = (A/128=4, L/64=4, B=64); 256 threads; 4x8 per thread.
// ---------------------------------------------------------------------------
__global__ void k3_main(const float* __restrict__ wh,
                        const float* __restrict__ pe1,
                        const float* __restrict__ pe2,
                        const float* __restrict__ W_pos,
                        const float* __restrict__ v) {
    const int a0 = blockIdx.x * 128;
    const int l0 = blockIdx.y * 64;
    const int b  = blockIdx.z;
    const int tid = threadIdx.x;
    const int tx = tid & 15;    // a group (8 cols)
    const int ty = tid >> 4;    // l group (4 rows)

    __shared__ float sA[16][65];     // [kt][lm]
    __shared__ float sB[16][128];    // [kt][an]
    __shared__ float sV[128];

    if (tid < 128) sV[tid] = v[a0 + tid];

    float acc[4][8];
#pragma unroll
    for (int r = 0; r < 4; r++)
#pragma unroll
        for (int c = 0; c < 8; c++) acc[r][c] = 0.f;

    const size_t whbase = ((size_t)b * L + l0) * H;
    const size_t pbase  = ((size_t)b * L + l0) * P;

    for (int k0 = 0; k0 < F; k0 += 16) {
#pragma unroll
        for (int i = 0; i < 4; i++) {
            int idx = tid + i * 256;
            int kt = idx & 15, lm = idx >> 4;
            int f = k0 + kt;
            float val;
            if (f < H)            val = wh[whbase + (size_t)lm * H + f];
            else if (f < H + P)   val = pe1[pbase + (size_t)lm * P + (f - H)];
            else                  val = pe2[pbase + (size_t)lm * P + (f - H - P)];
            sA[kt][lm] = val;
        }
#pragma unroll
        for (int i = 0; i < 8; i++) {
            int idx = tid + i * 256;
            int an = idx & 127, kt = idx >> 7;
            sB[kt][an] = W_pos[(size_t)(k0 + kt) * A + a0 + an];
        }
        __syncthreads();
#pragma unroll
        for (int kt = 0; kt < 16; kt++) {
            float aa[4];
#pragma unroll
            for (int r = 0; r < 4; r++) aa[r] = sA[kt][ty * 4 + r];
            float4 b0 = *(const float4*)&sB[kt][tx * 8];
            float4 b1 = *(const float4*)&sB[kt][tx * 8 + 4];
            float bb[8] = {b0.x, b0.y, b0.z, b0.w, b1.x, b1.y, b1.z, b1.w};
#pragma unroll
            for (int r = 0; r < 4; r++)
#pragma unroll
                for (int c = 0; c < 8; c++) acc[r][c] += aa[r] * bb[c];
        }
        __syncthreads();
    }

    // epilogue: tanh(+ent), dot with v, reduce across tx, atomic into vu
    const int half = (a0 >= 256) ? 1 : 0;
    float pv[4];
#pragma unroll
    for (int r = 0; r < 4; r++) {
        const int l = l0 + ty * 4 + r;
        const float e = g_dense_ent[b * A + 2 * l + half];
        float s = 0.f;
#pragma unroll
        for (int c = 0; c < 8; c++)
            s += sV[tx * 8 + c] * tanhf(acc[r][c] + e);
        pv[r] = s;
    }
#pragma unroll
    for (int off = 8; off; off >>= 1)
#pragma unroll
        for (int r = 0; r < 4; r++) pv[r] += __shfl_xor_sync(0xffffffffu, pv[r], off);
    if (tx == 0) {
#pragma unroll
        for (int r = 0; r < 4; r++)
            atomicAdd(&g_vu[b * L + l0 + ty * 4 + r], pv[r]);
    }
}

// ---------------------------------------------------------------------------
// K4: softmax over L + z = alpha-weighted sum of word_hiddens.
// grid = (B, H/256); 256 threads.
// ---------------------------------------------------------------------------
__global__ void k4_softmax_z(const float* __restrict__ wh, float* __restrict__ z) {
    const int b = blockIdx.x;
    const int hc = blockIdx.y;
    const int tid = threadIdx.x;
    const int lane = tid & 31;
    const int wid = tid >> 5;

    __shared__ float sa[L];
    __shared__ float red[8];

    float vu = g_vu[b * L + tid];

    // block max
    float m = vu;
#pragma unroll
    for (int off = 16; off; off >>= 1) m = fmaxf(m, __shfl_xor_sync(0xffffffffu, m, off));
    if (lane == 0) red[wid] = m;
    __syncthreads();
    if (tid < 8) {
        float mm = red[tid];
#pragma unroll
        for (int off = 4; off; off >>= 1) mm = fmaxf(mm, __shfl_xor_sync(0xffu, mm, off));
        if (tid == 0) red[0] = mm;
    }
    __syncthreads();
    m = red[0];
    __syncthreads();

    float e = expf(vu - m);
    float s = e;
#pragma unroll
    for (int off = 16; off; off >>= 1) s += __shfl_xor_sync(0xffffffffu, s, off);
    if (lane == 0) red[wid] = s;
    __syncthreads();
    if (tid < 8) {
        float ss = red[tid];
#pragma unroll
        for (int off = 4; off; off >>= 1) ss += __shfl_xor_sync(0xffu, ss, off);
        if (tid == 0) red[0] = ss;
    }
    __syncthreads();
    const float inv = 1.f / red[0];
    sa[tid] = e * inv;
    __syncthreads();

    const int h = hc * 256 + tid;
    const float* base = wh + (size_t)b * L * H + h;
    float acc = 0.f;
#pragma unroll 8
    for (int l = 0; l < L; l++) acc += sa[l] * base[(size_t)l * H];
    z[b * H + h] = acc;
}

// ---------------------------------------------------------------------------
extern "C" void kernel_launch(void* const* d_in, const int* in_sizes, int n_in,
                              void* d_out, int out_size) {
    const float* wh   = (const float*)d_in[0];  // [B,L,H]
    const float* pe1  = (const float*)d_in[1];  // [B,L,P]
    const float* pe2  = (const float*)d_in[2];  // [B,L,P]
    const int*   e1e  = (const int*)d_in[3];    // [B]
    const int*   e2e  = (const int*)d_in[4];    // [B]
    const float* te   = (const float*)d_in[5];  // [T,H]
    const float* Wp   = (const float*)d_in[6];  // [F,A]
    const float* We   = (const float*)d_in[7];  // [4H,A]
    const float* v    = (const float*)d_in[8];  // [A]
    float* z = (float*)d_out;                   // [B,H]

    k1_entity_prep<<<B, 256>>>(wh, e1e, e2e, te);
    k2_dense_ent<<<dim3(A / 64, 8), 256>>>(We);
    k3_main<<<dim3(A / 128, L / 64, B), 256>>>(wh, pe1, pe2, Wp, v);
    k4_softmax_z<<<dim3(B, H / 256), 256>>>(wh, z);
}

// round 3
// speedup vs baseline: 3.0896x; 3.0896x over previous
#include <cuda_runtime.h>
#include <cuda_fp16.h>
#include <math.h>
#include <stdint.h>

#define B 64
#define L 256
#define H 1024
#define P 64
#define A 512
#define T 8
#define F (H + 2 * P)   // 1152
#define M_TOT (B * L)   // 16384

// ---------------- scratch (device globals; no allocation allowed) ----------
__device__ float g_ef[B * 4 * H];            // entity_features [B, 4H]
__device__ float g_dense_ent[B * A];         // [B, A]
__device__ float g_vu[B * L];                // [B, L]
__device__ __half g_pf_h[M_TOT * F];         // pos_features hi  [M, F]
__device__ __half g_pf_l[M_TOT * F];         // pos_features lo
__device__ __half g_wp_h[A * F];             // W_pos^T hi  [A, F]
__device__ __half g_wp_l[A * F];             // W_pos^T lo

// ---------------- helpers --------------------------------------------------
__device__ __forceinline__ uint32_t smem_u32(const void* p) {
    uint32_t a;
    asm("{ .reg .u64 t; cvta.to.shared.u64 t, %1; cvt.u32.u64 %0, t; }" : "=r"(a) : "l"(p));
    return a;
}
__device__ __forceinline__ void split_f32(float x, __half& hi, __half& lo) {
    hi = __float2half_rn(x);
    lo = __float2half_rn(x - __half2float(hi));
}

#define CP_ASYNC16(smem, gmem) \
    asm volatile("cp.async.cg.shared.global [%0], [%1], 16;" :: "r"(smem), "l"(gmem))
#define CP_COMMIT() asm volatile("cp.async.commit_group;" ::: "memory")
#define CP_WAIT1()  asm volatile("cp.async.wait_group 1;" ::: "memory")

#define LDSM4(r0, r1, r2, r3, addr) \
    asm volatile("ldmatrix.sync.aligned.m8n8.x4.shared.b16 {%0,%1,%2,%3}, [%4];" \
        : "=r"(r0), "=r"(r1), "=r"(r2), "=r"(r3) : "r"(addr))

#define MMA16816(d, a, bb) \
    asm volatile("mma.sync.aligned.m16n8k16.row.col.f32.f16.f16.f32 " \
        "{%0,%1,%2,%3}, {%4,%5,%6,%7}, {%8,%9}, {%0,%1,%2,%3};" \
        : "+f"((d)[0]), "+f"((d)[1]), "+f"((d)[2]), "+f"((d)[3]) \
        : "r"((a)[0]), "r"((a)[1]), "r"((a)[2]), "r"((a)[3]), "r"((bb)[0]), "r"((bb)[1]))

// ---------------------------------------------------------------------------
// K0a: W_pos [F, A] -> transposed split halves g_wp_h/l [A, F].
// grid = (A/32, F/32) = (16, 36); 256 threads.
// ---------------------------------------------------------------------------
__global__ void k0a_split_wpos(const float* __restrict__ Wp) {
    __shared__ float tile[32][33];
    const int a0 = blockIdx.x * 32;
    const int f0 = blockIdx.y * 32;
    const int tx = threadIdx.x & 31;
    const int ty = threadIdx.x >> 5;   // 0..7
#pragma unroll
    for (int i = 0; i < 4; i++) {
        int f = ty + i * 8;
        tile[f][tx] = Wp[(size_t)(f0 + f) * A + a0 + tx];
    }
    __syncthreads();
#pragma unroll
    for (int i = 0; i < 4; i++) {
        int ar = ty + i * 8;           // a-row
        float x = tile[tx][ar];        // = Wp[f0+tx][a0+ar]
        __half hi, lo;
        split_f32(x, hi, lo);
        size_t o = (size_t)(a0 + ar) * F + f0 + tx;
        g_wp_h[o] = hi;
        g_wp_l[o] = lo;
    }
}

// ---------------------------------------------------------------------------
// K0b: pos_features = [wh | pe1 | pe2] split into hi/lo fp16 planes [M, F].
// grid = M_TOT blocks, 256 threads.
// ---------------------------------------------------------------------------
__global__ void k0b_split_pf(const float* __restrict__ wh,
                             const float* __restrict__ pe1,
                             const float* __restrict__ pe2) {
    const int m = blockIdx.x;
    const float* s0 = wh  + (size_t)m * H;
    const float* s1 = pe1 + (size_t)m * P;
    const float* s2 = pe2 + (size_t)m * P;
    __half* oh = g_pf_h + (size_t)m * F;
    __half* ol = g_pf_l + (size_t)m * F;
    for (int i = threadIdx.x; i < F / 4; i += 256) {
        int f4 = i * 4;
        float4 x;
        if (f4 < H)            x = *(const float4*)(s0 + f4);
        else if (f4 < H + P)   x = *(const float4*)(s1 + (f4 - H));
        else                   x = *(const float4*)(s2 + (f4 - H - P));
        __half h0, h1, h2, h3, q0, q1, q2, q3;
        split_f32(x.x, h0, q0); split_f32(x.y, h1, q1);
        split_f32(x.z, h2, q2); split_f32(x.w, h3, q3);
        __half2 hh[2] = {__halves2half2(h0, h1), __halves2half2(h2, h3)};
        __half2 ll[2] = {__halves2half2(q0, q1), __halves2half2(q2, q3)};
        *(uint2*)(oh + f4) = *(uint2*)hh;
        *(uint2*)(ol + f4) = *(uint2*)ll;
    }
}

// ---------------------------------------------------------------------------
// K1: entity gather + latent types + zero accumulators. grid=B, 256 threads.
// ---------------------------------------------------------------------------
__global__ void k1_entity_prep(const float* __restrict__ wh,
                               const int* __restrict__ e1_end,
                               const int* __restrict__ e2_end,
                               const float* __restrict__ te) {
    const int b = blockIdx.x;
    const int tid = threadIdx.x;
    const int lane = tid & 31;
    const int wid = tid >> 5;

    __shared__ float wsum[8][16];
    __shared__ float scores[16];
    __shared__ float alpha[2][T];

    const float* h1 = wh + ((size_t)b * L + e1_end[b]) * H;
    const float* h2 = wh + ((size_t)b * L + e2_end[b]) * H;

    float s[16];
#pragma unroll
    for (int i = 0; i < 16; i++) s[i] = 0.f;
    for (int h = tid; h < H; h += 256) {
        float v1 = h1[h], v2 = h2[h];
#pragma unroll
        for (int t = 0; t < T; t++) {
            float c = te[t * H + h];
            s[t] += v1 * c;
            s[8 + t] += v2 * c;
        }
    }
#pragma unroll
    for (int off = 16; off; off >>= 1)
#pragma unroll
        for (int i = 0; i < 16; i++) s[i] += __shfl_xor_sync(0xffffffffu, s[i], off);
    if (lane == 0)
#pragma unroll
        for (int i = 0; i < 16; i++) wsum[wid][i] = s[i];
    __syncthreads();
    if (tid < 16) {
        float tot = 0.f;
#pragma unroll
        for (int w = 0; w < 8; w++) tot += wsum[w][tid];
        scores[tid] = tot;
    }
    __syncthreads();
    if (tid < 2) {
        const float* sc = scores + tid * 8;
        float m = -1e30f;
#pragma unroll
        for (int i = 0; i < T; i++) m = fmaxf(m, sc[i]);
        float sum = 0.f;
        float e[T];
#pragma unroll
        for (int i = 0; i < T; i++) { e[i] = expf(sc[i] - m); sum += e[i]; }
        float inv = 1.f / sum;
#pragma unroll
        for (int i = 0; i < T; i++) alpha[tid][i] = e[i] * inv;
    }
    __syncthreads();

    float* ef = g_ef + (size_t)b * 4 * H;
    for (int h = tid; h < H; h += 256) {
        float t1 = 0.f, t2 = 0.f;
#pragma unroll
        for (int t = 0; t < T; t++) {
            float c = te[t * H + h];
            t1 += alpha[0][t] * c;
            t2 += alpha[1][t] * c;
        }
        ef[h]         = h1[h];
        ef[H + h]     = t1;
        ef[2 * H + h] = h2[h];
        ef[3 * H + h] = t2;
    }

    g_vu[b * L + tid] = 0.f;
    g_dense_ent[b * A + tid] = 0.f;
    g_dense_ent[b * A + 256 + tid] = 0.f;
}

// ---------------------------------------------------------------------------
// K2: dense_ent = ef[B,4H] @ W_ent[4H,A], split-K=16 atomic accumulate.
// grid = (8, 16); 256 threads; each thread 4x4.
// ---------------------------------------------------------------------------
__global__ void k2_dense_ent(const float* __restrict__ W_ent) {
    const int a0 = blockIdx.x * 64;
    const int k0 = blockIdx.y * 256;
    const int tid = threadIdx.x;
    const int tx = tid & 15;
    const int ty = tid >> 4;

    __shared__ float sE[16][65];
    __shared__ float sW[16][64];

    float acc[4][4];
#pragma unroll
    for (int r = 0; r < 4; r++)
#pragma unroll
        for (int c = 0; c < 4; c++) acc[r][c] = 0.f;

    for (int ks = 0; ks < 256; ks += 16) {
#pragma unroll
        for (int i = 0; i < 4; i++) {
            int idx = tid + i * 256;
            int kt = idx & 15, bb = idx >> 4;
            sE[kt][bb] = g_ef[(size_t)bb * (4 * H) + k0 + ks + kt];
        }
#pragma unroll
        for (int i = 0; i < 4; i++) {
            int idx = tid + i * 256;
            int an = idx & 63, kt = idx >> 6;
            sW[kt][an] = W_ent[(size_t)(k0 + ks + kt) * A + a0 + an];
        }
        __syncthreads();
#pragma unroll
        for (int kt = 0; kt < 16; kt++) {
            float e[4], w[4];
#pragma unroll
            for (int r = 0; r < 4; r++) e[r] = sE[kt][ty * 4 + r];
#pragma unroll
            for (int c = 0; c < 4; c++) w[c] = sW[kt][tx * 4 + c];
#pragma unroll
            for (int r = 0; r < 4; r++)
#pragma unroll
                for (int c = 0; c < 4; c++) acc[r][c] += e[r] * w[c];
        }
        __syncthreads();
    }
#pragma unroll
    for (int r = 0; r < 4; r++)
#pragma unroll
        for (int c = 0; c < 4; c++)
            atomicAdd(&g_dense_ent[(ty * 4 + r) * A + a0 + tx * 4 + c], acc[r][c]);
}

// ---------------------------------------------------------------------------
// K3: mma.sync fused GEMM (3xFP16 split) + tanh + v-dot -> vu.
// CTA 128(M) x 128(N), K=1152 in 36 chunks of 32; 3-stage cp.async pipeline.
// grid = (4, 128); 256 threads = 8 warps (2 M x 4 N), warp tile 64x32.
// ---------------------------------------------------------------------------
#define KT      32
#define PADK    40                      // halves per SMEM row (80 B, conflict-free)
#define MAT_SZ  (128 * PADK * 2)        // 10240 B per matrix plane
#define STG_SZ  (4 * MAT_SZ)            // Ah, Al, Bh, Bl = 40960 B
#define NSTG    3
#define K3_DSMEM (NSTG * STG_SZ)        // 122880 B
#define NKCH    (F / KT)                // 36

__global__ void __launch_bounds__(256, 1)
k3_main(const float* __restrict__ v) {
    extern __shared__ char dsm[];
    __shared__ float sv[128];

    const int n0 = blockIdx.x * 128;
    const int m0 = blockIdx.y * 128;
    const int b  = blockIdx.y >> 1;
    const int l0 = (blockIdx.y & 1) * 128;
    const int tid = threadIdx.x;
    const int lane = tid & 31;
    const int wid = tid >> 5;
    const int wm = wid >> 2;     // 0..1
    const int wn = wid & 3;      // 0..3

    if (tid < 128) sv[tid] = v[n0 + tid];
    const uint32_t sbase = smem_u32(dsm);

    // ---- async stage loader: 2048 x 16B transfers / stage, 8 per thread ----
    auto load_stage = [&](int t, int stg) {
        const int f0 = t * KT;
#pragma unroll
        for (int j = 0; j < 8; j++) {
            int id = tid + j * 256;            // 0..2047
            int mat = id >> 9;                 // 0 Ah, 1 Al, 2 Bh, 3 Bl
            int r   = (id >> 2) & 127;
            int ch  = id & 3;
            const __half* g =
                (mat == 0) ? g_pf_h : (mat == 1) ? g_pf_l :
                (mat == 2) ? g_wp_h : g_wp_l;
            int grow = ((mat < 2) ? m0 : n0) + r;
            const __half* gp = g + (size_t)grow * F + f0 + ch * 8;
            uint32_t sa = sbase + stg * STG_SZ + mat * MAT_SZ + r * (PADK * 2) + ch * 16;
            CP_ASYNC16(sa, gp);
        }
    };

    float acc[4][4][4];
#pragma unroll
    for (int mt = 0; mt < 4; mt++)
#pragma unroll
        for (int nt = 0; nt < 4; nt++)
#pragma unroll
            for (int i = 0; i < 4; i++) acc[mt][nt][i] = 0.f;

    load_stage(0, 0); CP_COMMIT();
    load_stage(1, 1); CP_COMMIT();

    for (int t = 0; t < NKCH; t++) {
        const int stg = t % NSTG;
        CP_WAIT1();
        __syncthreads();
        if (t + 2 < NKCH) load_stage(t + 2, (t + 2) % NSTG);
        CP_COMMIT();

        const uint32_t st = sbase + stg * STG_SZ;
#pragma unroll
        for (int kt = 0; kt < 2; kt++) {
            // A fragments (hi + lo): 4 m16 tiles
            uint32_t ah[4][4], al[4][4];
            const int acol = kt * 16 + ((lane >> 4) << 3);
#pragma unroll
            for (int mt = 0; mt < 4; mt++) {
                int row = wm * 64 + mt * 16 + (lane & 15);
                uint32_t ad = st + row * (PADK * 2) + acol * 2;
                LDSM4(ah[mt][0], ah[mt][1], ah[mt][2], ah[mt][3], ad);
                LDSM4(al[mt][0], al[mt][1], al[mt][2], al[mt][3], ad + MAT_SZ);
            }
            // B fragments (hi + lo): 4 n8 tiles via 2 x ldmatrix.x4 each plane
            uint32_t bh[4][2], bl[4][2];
            const int bcol = kt * 16 + ((lane & 8) ? 8 : 0);
            const int brow_in = (lane & 7) + ((lane & 16) ? 8 : 0);
#pragma unroll
            for (int pr = 0; pr < 2; pr++) {
                int row = wn * 32 + pr * 16 + brow_in;
                uint32_t bd = st + 2 * MAT_SZ + row * (PADK * 2) + bcol * 2;
                uint32_t r0, r1, r2, r3;
                LDSM4(r0, r1, r2, r3, bd);
                bh[pr * 2][0] = r0; bh[pr * 2][1] = r1;
                bh[pr * 2 + 1][0] = r2; bh[pr * 2 + 1][1] = r3;
                LDSM4(r0, r1, r2, r3, bd + MAT_SZ);
                bl[pr * 2][0] = r0; bl[pr * 2][1] = r1;
                bl[pr * 2 + 1][0] = r2; bl[pr * 2 + 1][1] = r3;
            }
#pragma unroll
            for (int mt = 0; mt < 4; mt++)
#pragma unroll
                for (int nt = 0; nt < 4; nt++) {
                    MMA16816(acc[mt][nt], ah[mt], bh[nt]);
                    MMA16816(acc[mt][nt], ah[mt], bl[nt]);
                    MMA16816(acc[mt][nt], al[mt], bh[nt]);
                }
        }
        __syncthreads();
    }

    // ---- epilogue: tanh(acc + ent) . v, reduce over quad, atomic into vu ---
    const int halfA = blockIdx.x >> 1;          // a<256 -> 0, else 1
#pragma unroll
    for (int mt = 0; mt < 4; mt++) {
#pragma unroll
        for (int h = 0; h < 2; h++) {
            const int l = l0 + wm * 64 + mt * 16 + (lane >> 2) + h * 8;
            const float e = g_dense_ent[b * A + 2 * l + halfA];
            float part = 0.f;
#pragma unroll
            for (int nt = 0; nt < 4; nt++) {
                int a = wn * 32 + nt * 8 + 2 * (lane & 3);
                part += sv[a]     * tanhf(acc[mt][nt][2 * h]     + e);
                part += sv[a + 1] * tanhf(acc[mt][nt][2 * h + 1] + e);
            }
            part += __shfl_xor_sync(0xffffffffu, part, 1);
            part += __shfl_xor_sync(0xffffffffu, part, 2);
            if ((lane & 3) == 0) atomicAdd(&g_vu[b * L + l], part);
        }
    }
}

// ---------------------------------------------------------------------------
// K4: softmax over L + z. grid = (B, H/256); 512 threads.
// ---------------------------------------------------------------------------
__global__ void k4_softmax_z(const float* __restrict__ wh, float* __restrict__ z) {
    const int b = blockIdx.x;
    const int hc = blockIdx.y;
    const int tid = threadIdx.x;
    const int lane = tid & 31;
    const int wid = tid >> 5;

    __shared__ float sa[L];
    __shared__ float red[16];
    __shared__ float part[512];

    float vu = (tid < 256) ? g_vu[b * L + tid] : -1e30f;

    float m = vu;
#pragma unroll
    for (int off = 16; off; off >>= 1) m = fmaxf(m, __shfl_xor_sync(0xffffffffu, m, off));
    if (lane == 0) red[wid] = m;
    __syncthreads();
    if (tid < 16) {
        float mm = red[tid];
#pragma unroll
        for (int off = 8; off; off >>= 1) mm = fmaxf(mm, __shfl_xor_sync(0xffffu, mm, off));
        if (tid == 0) red[0] = mm;
    }
    __syncthreads();
    const float mv = red[0];
    __syncthreads();

    float ex = (tid < 256) ? expf(vu - mv) : 0.f;
    float ssum = ex;
#pragma unroll
    for (int off = 16; off; off >>= 1) ssum += __shfl_xor_sync(0xffffffffu, ssum, off);
    if (lane == 0) red[wid] = ssum;
    __syncthreads();
    if (tid < 16) {
        float ss = red[tid];
#pragma unroll
        for (int off = 8; off; off >>= 1) ss += __shfl_xor_sync(0xffffu, ss, off);
        if (tid == 0) red[0] = ss;
    }
    __syncthreads();
    const float inv = 1.f / red[0];
    if (tid < 256) sa[tid] = ex * inv;
    __syncthreads();

    const int h = hc * 256 + (tid & 255);
    const int lh = tid >> 8;
    const float* base = wh + ((size_t)b * L + lh * 128) * H + h;
    float acc = 0.f;
#pragma unroll 8
    for (int l2 = 0; l2 < 128; l2++) acc += sa[lh * 128 + l2] * base[(size_t)l2 * H];
    part[tid] = acc;
    __syncthreads();
    if (tid < 256) z[b * H + h] = part[tid] + part[tid + 256];
}

// ---------------------------------------------------------------------------
extern "C" void kernel_launch(void* const* d_in, const int* in_sizes, int n_in,
                              void* d_out, int out_size) {
    const float* wh   = (const float*)d_in[0];
    const float* pe1  = (const float*)d_in[1];
    const float* pe2  = (const float*)d_in[2];
    const int*   e1e  = (const int*)d_in[3];
    const int*   e2e  = (const int*)d_in[4];
    const float* te   = (const float*)d_in[5];
    const float* Wp   = (const float*)d_in[6];
    const float* We   = (const float*)d_in[7];
    const float* v    = (const float*)d_in[8];
    float* z = (float*)d_out;

    cudaFuncSetAttribute(k3_main, cudaFuncAttributeMaxDynamicSharedMemorySize, K3_DSMEM);

    k0a_split_wpos<<<dim3(A / 32, F / 32), 256>>>(Wp);
    k0b_split_pf<<<M_TOT, 256>>>(wh, pe1, pe2);
    k1_entity_prep<<<B, 256>>>(wh, e1e, e2e, te);
    k2_dense_ent<<<dim3(8, 16), 256>>>(We);
    k3_main<<<dim3(4, 128), 256, K3_DSMEM>>>(v);
    k4_softmax_z<<<dim3(B, H / 256), 512>>>(wh, z);
}

// round 4
// speedup vs baseline: 3.5453x; 1.1475x over previous
#include <cuda_runtime.h>
#include <cuda_fp16.h>
#include <math.h>
#include <stdint.h>

#define B 64
#define L 256
#define H 1024
#define P 64
#define A 512
#define T 8
#define F (H + 2 * P)   // 1152
#define M_TOT (B * L)   // 16384

// ---------------- scratch (device globals; no allocation allowed) ----------
__device__ float g_ef[B * 4 * H];            // entity_features [B, 4H]
__device__ float g_dense_ent[B * A];         // [B, A]
__device__ float g_vu[B * L];                // [B, L]
__device__ float g_zp[4][B * H];             // z partials (split-L)
__device__ __half g_pf_h[M_TOT * F];         // pos_features hi  [M, F]
__device__ __half g_pf_l[M_TOT * F];         // pos_features lo
__device__ __half g_wp_h[A * F];             // W_pos^T hi  [A, F]
__device__ __half g_wp_l[A * F];             // W_pos^T lo

// ---------------- helpers --------------------------------------------------
__device__ __forceinline__ uint32_t smem_u32(const void* p) {
    uint32_t a;
    asm("{ .reg .u64 t; cvta.to.shared.u64 t, %1; cvt.u32.u64 %0, t; }" : "=r"(a) : "l"(p));
    return a;
}
__device__ __forceinline__ void split_f32(float x, __half& hi, __half& lo) {
    hi = __float2half_rn(x);
    lo = __float2half_rn(x - __half2float(hi));
}

#define CP_ASYNC16(smem, gmem) \
    asm volatile("cp.async.cg.shared.global [%0], [%1], 16;" :: "r"(smem), "l"(gmem))
#define CP_COMMIT() asm volatile("cp.async.commit_group;" ::: "memory")
#define CP_WAIT1()  asm volatile("cp.async.wait_group 1;" ::: "memory")
#define CP_WAIT0()  asm volatile("cp.async.wait_group 0;" ::: "memory")

#define LDSM4(r0, r1, r2, r3, addr) \
    asm volatile("ldmatrix.sync.aligned.m8n8.x4.shared.b16 {%0,%1,%2,%3}, [%4];" \
        : "=r"(r0), "=r"(r1), "=r"(r2), "=r"(r3) : "r"(addr))

#define MMA16816(d, a, bb) \
    asm volatile("mma.sync.aligned.m16n8k16.row.col.f32.f16.f16.f32 " \
        "{%0,%1,%2,%3}, {%4,%5,%6,%7}, {%8,%9}, {%0,%1,%2,%3};" \
        : "+f"((d)[0]), "+f"((d)[1]), "+f"((d)[2]), "+f"((d)[3]) \
        : "r"((a)[0]), "r"((a)[1]), "r"((a)[2]), "r"((a)[3]), "r"((bb)[0]), "r"((bb)[1]))

// ---------------------------------------------------------------------------
// K0a: W_pos [F, A] -> transposed split halves g_wp_h/l [A, F].
// ---------------------------------------------------------------------------
__global__ void k0a_split_wpos(const float* __restrict__ Wp) {
    __shared__ float tile[32][33];
    const int a0 = blockIdx.x * 32;
    const int f0 = blockIdx.y * 32;
    const int tx = threadIdx.x & 31;
    const int ty = threadIdx.x >> 5;
#pragma unroll
    for (int i = 0; i < 4; i++) {
        int f = ty + i * 8;
        tile[f][tx] = Wp[(size_t)(f0 + f) * A + a0 + tx];
    }
    __syncthreads();
#pragma unroll
    for (int i = 0; i < 4; i++) {
        int ar = ty + i * 8;
        float x = tile[tx][ar];
        __half hi, lo;
        split_f32(x, hi, lo);
        size_t o = (size_t)(a0 + ar) * F + f0 + tx;
        g_wp_h[o] = hi;
        g_wp_l[o] = lo;
    }
}

// ---------------------------------------------------------------------------
// K0b: pos_features = [wh | pe1 | pe2] split into hi/lo fp16 planes [M, F].
// ---------------------------------------------------------------------------
__global__ void k0b_split_pf(const float* __restrict__ wh,
                             const float* __restrict__ pe1,
                             const float* __restrict__ pe2) {
    const int m = blockIdx.x;
    const float* s0 = wh  + (size_t)m * H;
    const float* s1 = pe1 + (size_t)m * P;
    const float* s2 = pe2 + (size_t)m * P;
    __half* oh = g_pf_h + (size_t)m * F;
    __half* ol = g_pf_l + (size_t)m * F;
    for (int i = threadIdx.x; i < F / 4; i += 256) {
        int f4 = i * 4;
        float4 x;
        if (f4 < H)            x = *(const float4*)(s0 + f4);
        else if (f4 < H + P)   x = *(const float4*)(s1 + (f4 - H));
        else                   x = *(const float4*)(s2 + (f4 - H - P));
        __half h0, h1, h2, h3, q0, q1, q2, q3;
        split_f32(x.x, h0, q0); split_f32(x.y, h1, q1);
        split_f32(x.z, h2, q2); split_f32(x.w, h3, q3);
        __half2 hh[2] = {__halves2half2(h0, h1), __halves2half2(h2, h3)};
        __half2 ll[2] = {__halves2half2(q0, q1), __halves2half2(q2, q3)};
        *(uint2*)(oh + f4) = *(uint2*)hh;
        *(uint2*)(ol + f4) = *(uint2*)ll;
    }
}

// ---------------------------------------------------------------------------
// K1: entity gather + latent types + zero accumulators. grid=B, 256 threads.
// ---------------------------------------------------------------------------
__global__ void k1_entity_prep(const float* __restrict__ wh,
                               const int* __restrict__ e1_end,
                               const int* __restrict__ e2_end,
                               const float* __restrict__ te) {
    const int b = blockIdx.x;
    const int tid = threadIdx.x;
    const int lane = tid & 31;
    const int wid = tid >> 5;

    __shared__ float wsum[8][16];
    __shared__ float scores[16];
    __shared__ float alpha[2][T];

    const float* h1 = wh + ((size_t)b * L + e1_end[b]) * H;
    const float* h2 = wh + ((size_t)b * L + e2_end[b]) * H;

    float s[16];
#pragma unroll
    for (int i = 0; i < 16; i++) s[i] = 0.f;
    for (int h = tid; h < H; h += 256) {
        float v1 = h1[h], v2 = h2[h];
#pragma unroll
        for (int t = 0; t < T; t++) {
            float c = te[t * H + h];
            s[t] += v1 * c;
            s[8 + t] += v2 * c;
        }
    }
#pragma unroll
    for (int off = 16; off; off >>= 1)
#pragma unroll
        for (int i = 0; i < 16; i++) s[i] += __shfl_xor_sync(0xffffffffu, s[i], off);
    if (lane == 0)
#pragma unroll
        for (int i = 0; i < 16; i++) wsum[wid][i] = s[i];
    __syncthreads();
    if (tid < 16) {
        float tot = 0.f;
#pragma unroll
        for (int w = 0; w < 8; w++) tot += wsum[w][tid];
        scores[tid] = tot;
    }
    __syncthreads();
    if (tid < 2) {
        const float* sc = scores + tid * 8;
        float m = -1e30f;
#pragma unroll
        for (int i = 0; i < T; i++) m = fmaxf(m, sc[i]);
        float sum = 0.f;
        float e[T];
#pragma unroll
        for (int i = 0; i < T; i++) { e[i] = expf(sc[i] - m); sum += e[i]; }
        float inv = 1.f / sum;
#pragma unroll
        for (int i = 0; i < T; i++) alpha[tid][i] = e[i] * inv;
    }
    __syncthreads();

    float* ef = g_ef + (size_t)b * 4 * H;
    for (int h = tid; h < H; h += 256) {
        float t1 = 0.f, t2 = 0.f;
#pragma unroll
        for (int t = 0; t < T; t++) {
            float c = te[t * H + h];
            t1 += alpha[0][t] * c;
            t2 += alpha[1][t] * c;
        }
        ef[h]         = h1[h];
        ef[H + h]     = t1;
        ef[2 * H + h] = h2[h];
        ef[3 * H + h] = t2;
    }

    g_vu[b * L + tid] = 0.f;
    g_dense_ent[b * A + tid] = 0.f;
    g_dense_ent[b * A + 256 + tid] = 0.f;
}

// ---------------------------------------------------------------------------
// K2 v2: dense_ent = ef[B,4H] @ W_ent[4H,A]; cp.async burst then compute.
// grid = (8 a-tiles of 64, 32 k-splits of 128) = 256 CTAs; 256 threads.
// ---------------------------------------------------------------------------
__global__ void __launch_bounds__(256)
k2_dense_ent(const float* __restrict__ W_ent) {
    __shared__ float sE[64][132];   // [b][k]
    __shared__ float sW[128][68];   // [k][a]

    const int a0 = blockIdx.x * 64;
    const int k0 = blockIdx.y * 128;
    const int tid = threadIdx.x;

    // burst loads: 8 float4 each for sE and sW (MLP = 16)
#pragma unroll
    for (int j = 0; j < 8; j++) {
        int id = tid + j * 256;
        int r = id >> 5, c4 = (id & 31) * 4;
        CP_ASYNC16(smem_u32(&sE[r][c4]), g_ef + (size_t)r * (4 * H) + k0 + c4);
    }
#pragma unroll
    for (int j = 0; j < 8; j++) {
        int id = tid + j * 256;
        int r = id >> 4, c4 = (id & 15) * 4;
        CP_ASYNC16(smem_u32(&sW[r][c4]), W_ent + (size_t)(k0 + r) * A + a0 + c4);
    }
    CP_COMMIT();
    CP_WAIT0();
    __syncthreads();

    const int tx = tid & 15;
    const int ty = tid >> 4;
    float acc[4][4];
#pragma unroll
    for (int r = 0; r < 4; r++)
#pragma unroll
        for (int c = 0; c < 4; c++) acc[r][c] = 0.f;

#pragma unroll 8
    for (int kt = 0; kt < 128; kt++) {
        float4 w = *(const float4*)&sW[kt][tx * 4];
        float wv[4] = {w.x, w.y, w.z, w.w};
#pragma unroll
        for (int r = 0; r < 4; r++) {
            float e = sE[ty * 4 + r][kt];
#pragma unroll
            for (int c = 0; c < 4; c++) acc[r][c] += e * wv[c];
        }
    }
#pragma unroll
    for (int r = 0; r < 4; r++)
#pragma unroll
        for (int c = 0; c < 4; c++)
            atomicAdd(&g_dense_ent[(ty * 4 + r) * A + a0 + tx * 4 + c], acc[r][c]);
}

// ---------------------------------------------------------------------------
// K3: mma.sync fused GEMM (3xFP16 split) + tanh + v-dot -> vu.
// CTA 128(M) x 128(N), K=1152 in 18 chunks of 64; 2-stage cp.async pipeline.
// grid = (4, 128); 256 threads = 8 warps (2 M x 4 N), warp tile 64x32.
// ---------------------------------------------------------------------------
#define KT      64
#define PADK    72                      // halves per SMEM row (144 B, conflict-free)
#define MAT_SZ  (128 * PADK * 2)        // 18432 B per matrix plane
#define STG_SZ  (4 * MAT_SZ)            // Ah, Al, Bh, Bl = 73728 B
#define K3_DSMEM (2 * STG_SZ)           // 147456 B
#define NKCH    (F / KT)                // 18

__global__ void __launch_bounds__(256, 1)
k3_main(const float* __restrict__ v) {
    extern __shared__ char dsm[];
    __shared__ float sv[128];

    const int n0 = blockIdx.x * 128;
    const int m0 = blockIdx.y * 128;
    const int b  = blockIdx.y >> 1;
    const int l0 = (blockIdx.y & 1) * 128;
    const int tid = threadIdx.x;
    const int lane = tid & 31;
    const int wid = tid >> 5;
    const int wm = wid >> 2;     // 0..1
    const int wn = wid & 3;      // 0..3

    if (tid < 128) sv[tid] = v[n0 + tid];
    const uint32_t sbase = smem_u32(dsm);

    // precomputed load geometry: mat = j>>2 (compile-time), row = (j&3)*32 + rr
    const int rr   = tid >> 3;          // 0..31
    const int ch8  = (tid & 7) * 8;     // halves
    const int ch16 = (tid & 7) * 16;    // bytes
    const __half* gp0 = g_pf_h + (size_t)m0 * F + ch8;
    const __half* gp1 = g_pf_l + (size_t)m0 * F + ch8;
    const __half* gp2 = g_wp_h + (size_t)n0 * F + ch8;
    const __half* gp3 = g_wp_l + (size_t)n0 * F + ch8;

    auto load_stage = [&](int t, int stg) {
        const int f0 = t * KT;
        const uint32_t sb = sbase + stg * STG_SZ;
#pragma unroll
        for (int j = 0; j < 16; j++) {
            const int mat = j >> 2;
            const int r = (j & 3) * 32 + rr;
            const __half* src =
                ((mat == 0) ? gp0 : (mat == 1) ? gp1 : (mat == 2) ? gp2 : gp3)
                + (size_t)r * F + f0;
            uint32_t sa = sb + mat * MAT_SZ + r * (PADK * 2) + ch16;
            CP_ASYNC16(sa, src);
        }
    };

    float acc[4][4][4];
#pragma unroll
    for (int mt = 0; mt < 4; mt++)
#pragma unroll
        for (int nt = 0; nt < 4; nt++)
#pragma unroll
            for (int i = 0; i < 4; i++) acc[mt][nt][i] = 0.f;

    load_stage(0, 0); CP_COMMIT();

    for (int t = 0; t < NKCH; t++) {
        const int s = t & 1;
        if (t + 1 < NKCH) { load_stage(t + 1, s ^ 1); CP_COMMIT(); CP_WAIT1(); }
        else              { CP_WAIT0(); }
        __syncthreads();

        const uint32_t st = sbase + s * STG_SZ;
#pragma unroll
        for (int kt = 0; kt < 4; kt++) {
            // A fragments (hi + lo): 4 m16 tiles
            uint32_t ah[4][4], al[4][4];
            const int acol = kt * 16 + ((lane >> 4) << 3);
#pragma unroll
            for (int mt = 0; mt < 4; mt++) {
                int row = wm * 64 + mt * 16 + (lane & 15);
                uint32_t ad = st + row * (PADK * 2) + acol * 2;
                LDSM4(ah[mt][0], ah[mt][1], ah[mt][2], ah[mt][3], ad);
                LDSM4(al[mt][0], al[mt][1], al[mt][2], al[mt][3], ad + MAT_SZ);
            }
            // B fragments (hi + lo): 4 n8 tiles via 2 x ldmatrix.x4 each plane
            uint32_t bh[4][2], bl[4][2];
            const int bcol = kt * 16 + ((lane & 8) ? 8 : 0);
            const int brow_in = (lane & 7) + ((lane & 16) ? 8 : 0);
#pragma unroll
            for (int pr = 0; pr < 2; pr++) {
                int row = wn * 32 + pr * 16 + brow_in;
                uint32_t bd = st + 2 * MAT_SZ + row * (PADK * 2) + bcol * 2;
                uint32_t r0, r1, r2, r3;
                LDSM4(r0, r1, r2, r3, bd);
                bh[pr * 2][0] = r0; bh[pr * 2][1] = r1;
                bh[pr * 2 + 1][0] = r2; bh[pr * 2 + 1][1] = r3;
                LDSM4(r0, r1, r2, r3, bd + MAT_SZ);
                bl[pr * 2][0] = r0; bl[pr * 2][1] = r1;
                bl[pr * 2 + 1][0] = r2; bl[pr * 2 + 1][1] = r3;
            }
#pragma unroll
            for (int mt = 0; mt < 4; mt++)
#pragma unroll
                for (int nt = 0; nt < 4; nt++) {
                    MMA16816(acc[mt][nt], ah[mt], bh[nt]);
                    MMA16816(acc[mt][nt], ah[mt], bl[nt]);
                    MMA16816(acc[mt][nt], al[mt], bh[nt]);
                }
        }
        __syncthreads();
    }

    // ---- epilogue: tanh(acc + ent) . v, reduce over quad, atomic into vu ---
    const int halfA = blockIdx.x >> 1;          // a<256 -> 0, else 1
#pragma unroll
    for (int mt = 0; mt < 4; mt++) {
#pragma unroll
        for (int h = 0; h < 2; h++) {
            const int l = l0 + wm * 64 + mt * 16 + (lane >> 2) + h * 8;
            const float e = g_dense_ent[b * A + 2 * l + halfA];
            float part = 0.f;
#pragma unroll
            for (int nt = 0; nt < 4; nt++) {
                int a = wn * 32 + nt * 8 + 2 * (lane & 3);
                part += sv[a]     * tanhf(acc[mt][nt][2 * h]     + e);
                part += sv[a + 1] * tanhf(acc[mt][nt][2 * h + 1] + e);
            }
            part += __shfl_xor_sync(0xffffffffu, part, 1);
            part += __shfl_xor_sync(0xffffffffu, part, 2);
            if ((lane & 3) == 0) atomicAdd(&g_vu[b * L + l], part);
        }
    }
}

// ---------------------------------------------------------------------------
// K4: softmax over L + partial z (split-L x4). grid = (B, 4); 256 threads.
// ---------------------------------------------------------------------------
__global__ void __launch_bounds__(256)
k4_softmax_zp(const float* __restrict__ wh) {
    const int b = blockIdx.x;
    const int lq = blockIdx.y;
    const int tid = threadIdx.x;
    const int lane = tid & 31;
    const int wid = tid >> 5;

    __shared__ float sa[L];
    __shared__ float red[8];

    float vu = g_vu[b * L + tid];

    float m = vu;
#pragma unroll
    for (int off = 16; off; off >>= 1) m = fmaxf(m, __shfl_xor_sync(0xffffffffu, m, off));
    if (lane == 0) red[wid] = m;
    __syncthreads();
    if (tid < 8) {
        float mm = red[tid];
#pragma unroll
        for (int off = 4; off; off >>= 1) mm = fmaxf(mm, __shfl_xor_sync(0xffu, mm, off));
        if (tid == 0) red[0] = mm;
    }
    __syncthreads();
    const float mv = red[0];
    __syncthreads();

    float ex = expf(vu - mv);
    float ssum = ex;
#pragma unroll
    for (int off = 16; off; off >>= 1) ssum += __shfl_xor_sync(0xffffffffu, ssum, off);
    if (lane == 0) red[wid] = ssum;
    __syncthreads();
    if (tid < 8) {
        float ss = red[tid];
#pragma unroll
        for (int off = 4; off; off >>= 1) ss += __shfl_xor_sync(0xffu, ss, off);
        if (tid == 0) red[0] = ss;
    }
    __syncthreads();
    const float inv = 1.f / red[0];
    sa[tid] = ex * inv;
    __syncthreads();

    const int h4 = tid * 4;
    const float* base = wh + ((size_t)b * L + lq * 64) * H + h4;
    float ax = 0.f, ay = 0.f, az = 0.f, aw = 0.f;
#pragma unroll 8
    for (int l2 = 0; l2 < 64; l2++) {
        float4 x = *(const float4*)(base + (size_t)l2 * H);
        float s = sa[lq * 64 + l2];
        ax += s * x.x; ay += s * x.y; az += s * x.z; aw += s * x.w;
    }
    float4 o = {ax, ay, az, aw};
    *(float4*)(&g_zp[lq][b * H + h4]) = o;
}

// ---------------------------------------------------------------------------
// K5: z = sum of 4 partials. 64 blocks x 256 threads, float4 per thread.
// ---------------------------------------------------------------------------
__global__ void k5_combine(float* __restrict__ z) {
    const int i4 = (blockIdx.x * 256 + threadIdx.x) * 4;
    float4 a = *(const float4*)&g_zp[0][i4];
    float4 b = *(const float4*)&g_zp[1][i4];
    float4 c = *(const float4*)&g_zp[2][i4];
    float4 d = *(const float4*)&g_zp[3][i4];
    float4 o = {a.x + b.x + c.x + d.x, a.y + b.y + c.y + d.y,
                a.z + b.z + c.z + d.z, a.w + b.w + c.w + d.w};
    *(float4*)(z + i4) = o;
}

// ---------------------------------------------------------------------------
extern "C" void kernel_launch(void* const* d_in, const int* in_sizes, int n_in,
                              void* d_out, int out_size) {
    const float* wh   = (const float*)d_in[0];
    const float* pe1  = (const float*)d_in[1];
    const float* pe2  = (const float*)d_in[2];
    const int*   e1e  = (const int*)d_in[3];
    const int*   e2e  = (const int*)d_in[4];
    const float* te   = (const float*)d_in[5];
    const float* Wp   = (const float*)d_in[6];
    const float* We   = (const float*)d_in[7];
    const float* v    = (const float*)d_in[8];
    float* z = (float*)d_out;

    cudaFuncSetAttribute(k3_main, cudaFuncAttributeMaxDynamicSharedMemorySize, K3_DSMEM);

    k0a_split_wpos<<<dim3(A / 32, F / 32), 256>>>(Wp);
    k0b_split_pf<<<M_TOT, 256>>>(wh, pe1, pe2);
    k1_entity_prep<<<B, 256>>>(wh, e1e, e2e, te);
    k2_dense_ent<<<dim3(8, 32), 256>>>(We);
    k3_main<<<dim3(4, 128), 256, K3_DSMEM>>>(v);
    k4_softmax_zp<<<dim3(B, 4), 256>>>(wh);
    k5_combine<<<64, 256>>>(z);
}

// round 5
// speedup vs baseline: 3.7573x; 1.0598x over previous
#include <cuda_runtime.h>
#include <cuda_fp16.h>
#include <math.h>
#include <stdint.h>

#define B 64
#define L 256
#define H 1024
#define P 64
#define A 512
#define T 8
#define F (H + 2 * P)   // 1152
#define M_TOT (B * L)   // 16384

// ---------------- scratch (device globals; no allocation allowed) ----------
__device__ float g_ef[B * 4 * H];            // entity_features [B, 4H]
__device__ float g_dense_ent[B * A];         // [B, A]
__device__ float g_vu[B * L];                // [B, L]
__device__ float g_zp[4][B * H];             // z partials (split-L)
__device__ __half g_pf_h[M_TOT * F];         // pos_features hi  [M, F]
__device__ __half g_pf_l[M_TOT * F];         // pos_features lo
__device__ __half g_wp_h[A * F];             // W_pos^T hi  [A, F]
__device__ __half g_wp_l[A * F];             // W_pos^T lo

// ---------------- helpers --------------------------------------------------
__device__ __forceinline__ uint32_t smem_u32(const void* p) {
    uint32_t a;
    asm("{ .reg .u64 t; cvta.to.shared.u64 t, %1; cvt.u32.u64 %0, t; }" : "=r"(a) : "l"(p));
    return a;
}
__device__ __forceinline__ void split_f32(float x, __half& hi, __half& lo) {
    hi = __float2half_rn(x);
    lo = __float2half_rn(x - __half2float(hi));
}

#define CP_ASYNC16(smem, gmem) \
    asm volatile("cp.async.cg.shared.global [%0], [%1], 16;" :: "r"(smem), "l"(gmem))
#define CP_COMMIT() asm volatile("cp.async.commit_group;" ::: "memory")
#define CP_WAIT1()  asm volatile("cp.async.wait_group 1;" ::: "memory")
#define CP_WAIT0()  asm volatile("cp.async.wait_group 0;" ::: "memory")

#define LDSM4(r0, r1, r2, r3, addr) \
    asm volatile("ldmatrix.sync.aligned.m8n8.x4.shared.b16 {%0,%1,%2,%3}, [%4];" \
        : "=r"(r0), "=r"(r1), "=r"(r2), "=r"(r3) : "r"(addr))

#define MMA16816(d, a, bb) \
    asm volatile("mma.sync.aligned.m16n8k16.row.col.f32.f16.f16.f32 " \
        "{%0,%1,%2,%3}, {%4,%5,%6,%7}, {%8,%9}, {%0,%1,%2,%3};" \
        : "+f"((d)[0]), "+f"((d)[1]), "+f"((d)[2]), "+f"((d)[3]) \
        : "r"((a)[0]), "r"((a)[1]), "r"((a)[2]), "r"((a)[3]), "r"((bb)[0]), "r"((bb)[1]))

// ---------------------------------------------------------------------------
// K0a: W_pos [F, A] -> transposed split halves g_wp_h/l [A, F].
// ---------------------------------------------------------------------------
__global__ void k0a_split_wpos(const float* __restrict__ Wp) {
    __shared__ float tile[32][33];
    const int a0 = blockIdx.x * 32;
    const int f0 = blockIdx.y * 32;
    const int tx = threadIdx.x & 31;
    const int ty = threadIdx.x >> 5;
#pragma unroll
    for (int i = 0; i < 4; i++) {
        int f = ty + i * 8;
        tile[f][tx] = Wp[(size_t)(f0 + f) * A + a0 + tx];
    }
    __syncthreads();
#pragma unroll
    for (int i = 0; i < 4; i++) {
        int ar = ty + i * 8;
        float x = tile[tx][ar];
        __half hi, lo;
        split_f32(x, hi, lo);
        size_t o = (size_t)(a0 + ar) * F + f0 + tx;
        g_wp_h[o] = hi;
        g_wp_l[o] = lo;
    }
}

// ---------------------------------------------------------------------------
// K0b: pos_features = [wh | pe1 | pe2] split into hi/lo fp16 planes [M, F].
// ---------------------------------------------------------------------------
__global__ void k0b_split_pf(const float* __restrict__ wh,
                             const float* __restrict__ pe1,
                             const float* __restrict__ pe2) {
    const int m = blockIdx.x;
    const float* s0 = wh  + (size_t)m * H;
    const float* s1 = pe1 + (size_t)m * P;
    const float* s2 = pe2 + (size_t)m * P;
    __half* oh = g_pf_h + (size_t)m * F;
    __half* ol = g_pf_l + (size_t)m * F;
    for (int i = threadIdx.x; i < F / 4; i += 256) {
        int f4 = i * 4;
        float4 x;
        if (f4 < H)            x = *(const float4*)(s0 + f4);
        else if (f4 < H + P)   x = *(const float4*)(s1 + (f4 - H));
        else                   x = *(const float4*)(s2 + (f4 - H - P));
        __half h0, h1, h2, h3, q0, q1, q2, q3;
        split_f32(x.x, h0, q0); split_f32(x.y, h1, q1);
        split_f32(x.z, h2, q2); split_f32(x.w, h3, q3);
        __half2 hh[2] = {__halves2half2(h0, h1), __halves2half2(h2, h3)};
        __half2 ll[2] = {__halves2half2(q0, q1), __halves2half2(q2, q3)};
        *(uint2*)(oh + f4) = *(uint2*)hh;
        *(uint2*)(ol + f4) = *(uint2*)ll;
    }
}

// ---------------------------------------------------------------------------
// K1: entity gather + latent types + zero accumulators. grid=B, 256 threads.
// ---------------------------------------------------------------------------
__global__ void k1_entity_prep(const float* __restrict__ wh,
                               const int* __restrict__ e1_end,
                               const int* __restrict__ e2_end,
                               const float* __restrict__ te) {
    const int b = blockIdx.x;
    const int tid = threadIdx.x;
    const int lane = tid & 31;
    const int wid = tid >> 5;

    __shared__ float wsum[8][16];
    __shared__ float scores[16];
    __shared__ float alpha[2][T];

    const float* h1 = wh + ((size_t)b * L + e1_end[b]) * H;
    const float* h2 = wh + ((size_t)b * L + e2_end[b]) * H;

    float s[16];
#pragma unroll
    for (int i = 0; i < 16; i++) s[i] = 0.f;
    for (int h = tid; h < H; h += 256) {
        float v1 = h1[h], v2 = h2[h];
#pragma unroll
        for (int t = 0; t < T; t++) {
            float c = te[t * H + h];
            s[t] += v1 * c;
            s[8 + t] += v2 * c;
        }
    }
#pragma unroll
    for (int off = 16; off; off >>= 1)
#pragma unroll
        for (int i = 0; i < 16; i++) s[i] += __shfl_xor_sync(0xffffffffu, s[i], off);
    if (lane == 0)
#pragma unroll
        for (int i = 0; i < 16; i++) wsum[wid][i] = s[i];
    __syncthreads();
    if (tid < 16) {
        float tot = 0.f;
#pragma unroll
        for (int w = 0; w < 8; w++) tot += wsum[w][tid];
        scores[tid] = tot;
    }
    __syncthreads();
    if (tid < 2) {
        const float* sc = scores + tid * 8;
        float m = -1e30f;
#pragma unroll
        for (int i = 0; i < T; i++) m = fmaxf(m, sc[i]);
        float sum = 0.f;
        float e[T];
#pragma unroll
        for (int i = 0; i < T; i++) { e[i] = expf(sc[i] - m); sum += e[i]; }
        float inv = 1.f / sum;
#pragma unroll
        for (int i = 0; i < T; i++) alpha[tid][i] = e[i] * inv;
    }
    __syncthreads();

    float* ef = g_ef + (size_t)b * 4 * H;
    for (int h = tid; h < H; h += 256) {
        float t1 = 0.f, t2 = 0.f;
#pragma unroll
        for (int t = 0; t < T; t++) {
            float c = te[t * H + h];
            t1 += alpha[0][t] * c;
            t2 += alpha[1][t] * c;
        }
        ef[h]         = h1[h];
        ef[H + h]     = t1;
        ef[2 * H + h] = h2[h];
        ef[3 * H + h] = t2;
    }

    g_vu[b * L + tid] = 0.f;
    g_dense_ent[b * A + tid] = 0.f;
    g_dense_ent[b * A + 256 + tid] = 0.f;
}

// ---------------------------------------------------------------------------
// K2 v3: dense_ent = ef[B,4H] @ W_ent[4H,A]; cp.async burst then compute.
// grid = (8 a-tiles of 64, 64 k-splits of 64) = 512 CTAs; 256 threads.
// ---------------------------------------------------------------------------
__global__ void __launch_bounds__(256)
k2_dense_ent(const float* __restrict__ W_ent) {
    __shared__ float sE[64][68];   // [b][k]
    __shared__ float sW[64][68];   // [k][a]

    const int a0 = blockIdx.x * 64;
    const int k0 = blockIdx.y * 64;
    const int tid = threadIdx.x;

#pragma unroll
    for (int j = 0; j < 4; j++) {
        int id = tid + j * 256;
        int r = id >> 4, c4 = (id & 15) * 4;
        CP_ASYNC16(smem_u32(&sE[r][c4]), g_ef + (size_t)r * (4 * H) + k0 + c4);
    }
#pragma unroll
    for (int j = 0; j < 4; j++) {
        int id = tid + j * 256;
        int r = id >> 4, c4 = (id & 15) * 4;
        CP_ASYNC16(smem_u32(&sW[r][c4]), W_ent + (size_t)(k0 + r) * A + a0 + c4);
    }
    CP_COMMIT();
    CP_WAIT0();
    __syncthreads();

    const int tx = tid & 15;
    const int ty = tid >> 4;
    float acc[4][4];
#pragma unroll
    for (int r = 0; r < 4; r++)
#pragma unroll
        for (int c = 0; c < 4; c++) acc[r][c] = 0.f;

#pragma unroll 8
    for (int kt = 0; kt < 64; kt++) {
        float4 w = *(const float4*)&sW[kt][tx * 4];
        float wv[4] = {w.x, w.y, w.z, w.w};
#pragma unroll
        for (int r = 0; r < 4; r++) {
            float e = sE[ty * 4 + r][kt];
#pragma unroll
            for (int c = 0; c < 4; c++) acc[r][c] += e * wv[c];
        }
    }
#pragma unroll
    for (int r = 0; r < 4; r++)
#pragma unroll
        for (int c = 0; c < 4; c++)
            atomicAdd(&g_dense_ent[(ty * 4 + r) * A + a0 + tx * 4 + c], acc[r][c]);
}

// ---------------------------------------------------------------------------
// K3: mma.sync fused GEMM (3xFP16 split) + tanh + v-dot -> vu.
// CTA 128(M) x 256(N), K=1152 in 18 chunks of 64; 2-stage cp.async pipeline.
// grid = (2, 128); 256 threads = 8 warps (2 M x 4 N), warp tile 64x64.
// ---------------------------------------------------------------------------
#define KT      64
#define PADK    72                      // halves per SMEM row (144 B, conflict-free)
#define A_SZ    (128 * PADK * 2)        // 18432 B per A plane
#define B_SZ    (256 * PADK * 2)        // 36864 B per B plane
#define OFF_AH  0
#define OFF_AL  (A_SZ)
#define OFF_BH  (2 * A_SZ)
#define OFF_BL  (2 * A_SZ + B_SZ)
#define STG_SZ  (2 * A_SZ + 2 * B_SZ)   // 110592 B
#define K3_DSMEM (2 * STG_SZ)           // 221184 B
#define NKCH    (F / KT)                // 18

__global__ void __launch_bounds__(256, 1)
k3_main(const float* __restrict__ v) {
    extern __shared__ char dsm[];
    __shared__ float sv[256];

    const int n0 = blockIdx.x * 256;
    const int m0 = blockIdx.y * 128;
    const int b  = blockIdx.y >> 1;
    const int l0 = (blockIdx.y & 1) * 128;
    const int tid = threadIdx.x;
    const int lane = tid & 31;
    const int wid = tid >> 5;
    const int wm = wid >> 2;     // 0..1, m-offset 64
    const int wn = wid & 3;      // 0..3, n-offset 64

    sv[tid] = v[n0 + tid];
    const uint32_t sbase = smem_u32(dsm);

    // load geometry: 6144 x 16B per stage, 24 per thread
    const int rr   = tid >> 3;          // 0..31
    const int ch8  = (tid & 7) * 8;     // halves
    const int ch16 = (tid & 7) * 16;    // bytes
    const __half* gp0 = g_pf_h + (size_t)m0 * F + ch8;
    const __half* gp1 = g_pf_l + (size_t)m0 * F + ch8;
    const __half* gp2 = g_wp_h + (size_t)n0 * F + ch8;
    const __half* gp3 = g_wp_l + (size_t)n0 * F + ch8;

    auto load_stage = [&](int t, int stg) {
        const int f0 = t * KT;
        const uint32_t sb = sbase + stg * STG_SZ;
        // Ah: j 0..3 (128 rows), Al: j 4..7, Bh: j 8..15 (256 rows), Bl: j 16..23
#pragma unroll
        for (int j = 0; j < 4; j++) {
            int r = rr + j * 32;
            CP_ASYNC16(sb + OFF_AH + r * (PADK * 2) + ch16, gp0 + (size_t)r * F + f0);
        }
#pragma unroll
        for (int j = 0; j < 4; j++) {
            int r = rr + j * 32;
            CP_ASYNC16(sb + OFF_AL + r * (PADK * 2) + ch16, gp1 + (size_t)r * F + f0);
        }
#pragma unroll
        for (int j = 0; j < 8; j++) {
            int r = rr + j * 32;
            CP_ASYNC16(sb + OFF_BH + r * (PADK * 2) + ch16, gp2 + (size_t)r * F + f0);
        }
#pragma unroll
        for (int j = 0; j < 8; j++) {
            int r = rr + j * 32;
            CP_ASYNC16(sb + OFF_BL + r * (PADK * 2) + ch16, gp3 + (size_t)r * F + f0);
        }
    };

    float acc[4][8][4];
#pragma unroll
    for (int mt = 0; mt < 4; mt++)
#pragma unroll
        for (int nt = 0; nt < 8; nt++)
#pragma unroll
            for (int i = 0; i < 4; i++) acc[mt][nt][i] = 0.f;

    load_stage(0, 0); CP_COMMIT();

    for (int t = 0; t < NKCH; t++) {
        const int s = t & 1;
        if (t + 1 < NKCH) { load_stage(t + 1, s ^ 1); CP_COMMIT(); CP_WAIT1(); }
        else              { CP_WAIT0(); }
        __syncthreads();

        const uint32_t st = sbase + s * STG_SZ;
#pragma unroll
        for (int kt = 0; kt < 4; kt++) {
            // A fragments (hi + lo): 4 m16 tiles
            uint32_t ah[4][4], al[4][4];
            const int acol = kt * 16 + ((lane >> 4) << 3);
#pragma unroll
            for (int mt = 0; mt < 4; mt++) {
                int row = wm * 64 + mt * 16 + (lane & 15);
                uint32_t ad = st + row * (PADK * 2) + acol * 2;
                LDSM4(ah[mt][0], ah[mt][1], ah[mt][2], ah[mt][3], ad + OFF_AH);
                LDSM4(al[mt][0], al[mt][1], al[mt][2], al[mt][3], ad + OFF_AL);
            }
            // B fragments loaded per 16-row pair to cap live registers
            const int bcol = kt * 16 + ((lane & 8) ? 8 : 0);
            const int brow_in = (lane & 7) + ((lane & 16) ? 8 : 0);
#pragma unroll
            for (int pr = 0; pr < 4; pr++) {
                int row = wn * 64 + pr * 16 + brow_in;
                uint32_t bd = st + row * (PADK * 2) + bcol * 2;
                uint32_t bh0[2], bh1[2], bl0[2], bl1[2];
                uint32_t r0, r1, r2, r3;
                LDSM4(r0, r1, r2, r3, bd + OFF_BH);
                bh0[0] = r0; bh0[1] = r1; bh1[0] = r2; bh1[1] = r3;
                LDSM4(r0, r1, r2, r3, bd + OFF_BL);
                bl0[0] = r0; bl0[1] = r1; bl1[0] = r2; bl1[1] = r3;
#pragma unroll
                for (int mt = 0; mt < 4; mt++) {
                    MMA16816(acc[mt][pr * 2], ah[mt], bh0);
                    MMA16816(acc[mt][pr * 2], ah[mt], bl0);
                    MMA16816(acc[mt][pr * 2], al[mt], bh0);
                    MMA16816(acc[mt][pr * 2 + 1], ah[mt], bh1);
                    MMA16816(acc[mt][pr * 2 + 1], ah[mt], bl1);
                    MMA16816(acc[mt][pr * 2 + 1], al[mt], bh1);
                }
            }
        }
        __syncthreads();
    }

    // ---- epilogue: tanh(acc + ent) . v, reduce over quad, atomic into vu ---
    const int halfA = blockIdx.x;               // n0=0 -> 0, n0=256 -> 1
#pragma unroll
    for (int mt = 0; mt < 4; mt++) {
#pragma unroll
        for (int h = 0; h < 2; h++) {
            const int l = l0 + wm * 64 + mt * 16 + (lane >> 2) + h * 8;
            const float e = g_dense_ent[b * A + 2 * l + halfA];
            float part = 0.f;
#pragma unroll
            for (int nt = 0; nt < 8; nt++) {
                int a = wn * 64 + nt * 8 + 2 * (lane & 3);
                part += sv[a]     * tanhf(acc[mt][nt][2 * h]     + e);
                part += sv[a + 1] * tanhf(acc[mt][nt][2 * h + 1] + e);
            }
            part += __shfl_xor_sync(0xffffffffu, part, 1);
            part += __shfl_xor_sync(0xffffffffu, part, 2);
            if ((lane & 3) == 0) atomicAdd(&g_vu[b * L + l], part);
        }
    }
}

// ---------------------------------------------------------------------------
// K4: softmax over L + partial z (split-L x4). grid = (B, 4); 256 threads.
// ---------------------------------------------------------------------------
__global__ void __launch_bounds__(256)
k4_softmax_zp(const float* __restrict__ wh) {
    const int b = blockIdx.x;
    const int lq = blockIdx.y;
    const int tid = threadIdx.x;
    const int lane = tid & 31;
    const int wid = tid >> 5;

    __shared__ float sa[L];
    __shared__ float red[8];

    float vu = g_vu[b * L + tid];

    float m = vu;
#pragma unroll
    for (int off = 16; off; off >>= 1) m = fmaxf(m, __shfl_xor_sync(0xffffffffu, m, off));
    if (lane == 0) red[wid] = m;
    __syncthreads();
    if (tid < 8) {
        float mm = red[tid];
#pragma unroll
        for (int off = 4; off; off >>= 1) mm = fmaxf(mm, __shfl_xor_sync(0xffu, mm, off));
        if (tid == 0) red[0] = mm;
    }
    __syncthreads();
    const float mv = red[0];
    __syncthreads();

    float ex = expf(vu - mv);
    float ssum = ex;
#pragma unroll
    for (int off = 16; off; off >>= 1) ssum += __shfl_xor_sync(0xffffffffu, ssum, off);
    if (lane == 0) red[wid] = ssum;
    __syncthreads();
    if (tid < 8) {
        float ss = red[tid];
#pragma unroll
        for (int off = 4; off; off >>= 1) ss += __shfl_xor_sync(0xffu, ss, off);
        if (tid == 0) red[0] = ss;
    }
    __syncthreads();
    const float inv = 1.f / red[0];
    sa[tid] = ex * inv;
    __syncthreads();

    const int h4 = tid * 4;
    const float* base = wh + ((size_t)b * L + lq * 64) * H + h4;
    float ax = 0.f, ay = 0.f, az = 0.f, aw = 0.f;
#pragma unroll 8
    for (int l2 = 0; l2 < 64; l2++) {
        float4 x = *(const float4*)(base + (size_t)l2 * H);
        float s = sa[lq * 64 + l2];
        ax += s * x.x; ay += s * x.y; az += s * x.z; aw += s * x.w;
    }
    float4 o = {ax, ay, az, aw};
    *(float4*)(&g_zp[lq][b * H + h4]) = o;
}

// ---------------------------------------------------------------------------
// K5: z = sum of 4 partials. 64 blocks x 256 threads, float4 per thread.
// ---------------------------------------------------------------------------
__global__ void k5_combine(float* __restrict__ z) {
    const int i4 = (blockIdx.x * 256 + threadIdx.x) * 4;
    float4 a = *(const float4*)&g_zp[0][i4];
    float4 b = *(const float4*)&g_zp[1][i4];
    float4 c = *(const float4*)&g_zp[2][i4];
    float4 d = *(const float4*)&g_zp[3][i4];
    float4 o = {a.x + b.x + c.x + d.x, a.y + b.y + c.y + d.y,
                a.z + b.z + c.z + d.z, a.w + b.w + c.w + d.w};
    *(float4*)(z + i4) = o;
}

// ---------------------------------------------------------------------------
extern "C" void kernel_launch(void* const* d_in, const int* in_sizes, int n_in,
                              void* d_out, int out_size) {
    const float* wh   = (const float*)d_in[0];
    const float* pe1  = (const float*)d_in[1];
    const float* pe2  = (const float*)d_in[2];
    const int*   e1e  = (const int*)d_in[3];
    const int*   e2e  = (const int*)d_in[4];
    const float* te   = (const float*)d_in[5];
    const float* Wp   = (const float*)d_in[6];
    const float* We   = (const float*)d_in[7];
    const float* v    = (const float*)d_in[8];
    float* z = (float*)d_out;

    cudaFuncSetAttribute(k3_main, cudaFuncAttributeMaxDynamicSharedMemorySize, K3_DSMEM);

    k0a_split_wpos<<<dim3(A / 32, F / 32), 256>>>(Wp);
    k0b_split_pf<<<M_TOT, 256>>>(wh, pe1, pe2);
    k1_entity_prep<<<B, 256>>>(wh, e1e, e2e, te);
    k2_dense_ent<<<dim3(8, 64), 256>>>(We);
    k3_main<<<dim3(2, 128), 256, K3_DSMEM>>>(v);
    k4_softmax_zp<<<dim3(B, 4), 256>>>(wh);
    k5_combine<<<64, 256>>>(z);
}

// round 6
// speedup vs baseline: 4.8451x; 1.2895x over previous
#include <cuda_runtime.h>
#include <cuda_fp16.h>
#include <math.h>
#include <stdint.h>

#define B 64
#define L 256
#define H 1024
#define P 64
#define A 512
#define T 8
#define F (H + 2 * P)   // 1152
#define M_TOT (B * L)   // 16384

// ---------------- scratch (device globals; no allocation allowed) ----------
__device__ float g_ef[B * 4 * H];            // entity_features [B, 4H]
__device__ float g_dense_ent[B * A];         // [B, A]
__device__ float g_vu[B * L];                // [B, L]
__device__ float g_zp[4][B * H];             // z partials (split-L)
__device__ __half g_pf_h[M_TOT * F];         // pos_features fp16 [M, F]
__device__ __half g_wp_h[A * F];             // W_pos^T hi  [A, F]
__device__ __half g_wp_l[A * F];             // W_pos^T lo

// ---------------- helpers --------------------------------------------------
__device__ __forceinline__ uint32_t smem_u32(const void* p) {
    uint32_t a;
    asm("{ .reg .u64 t; cvta.to.shared.u64 t, %1; cvt.u32.u64 %0, t; }" : "=r"(a) : "l"(p));
    return a;
}
__device__ __forceinline__ void split_f32(float x, __half& hi, __half& lo) {
    hi = __float2half_rn(x);
    lo = __float2half_rn(x - __half2float(hi));
}

#define CP_ASYNC16(smem, gmem) \
    asm volatile("cp.async.cg.shared.global [%0], [%1], 16;" :: "r"(smem), "l"(gmem))
#define CP_COMMIT() asm volatile("cp.async.commit_group;" ::: "memory")
#define CP_WAIT1()  asm volatile("cp.async.wait_group 1;" ::: "memory")
#define CP_WAIT0()  asm volatile("cp.async.wait_group 0;" ::: "memory")

#define LDSM4(r0, r1, r2, r3, addr) \
    asm volatile("ldmatrix.sync.aligned.m8n8.x4.shared.b16 {%0,%1,%2,%3}, [%4];" \
        : "=r"(r0), "=r"(r1), "=r"(r2), "=r"(r3) : "r"(addr))

#define MMA16816(d, a, bb) \
    asm volatile("mma.sync.aligned.m16n8k16.row.col.f32.f16.f16.f32 " \
        "{%0,%1,%2,%3}, {%4,%5,%6,%7}, {%8,%9}, {%0,%1,%2,%3};" \
        : "+f"((d)[0]), "+f"((d)[1]), "+f"((d)[2]), "+f"((d)[3]) \
        : "r"((a)[0]), "r"((a)[1]), "r"((a)[2]), "r"((a)[3]), "r"((bb)[0]), "r"((bb)[1]))

// ---------------------------------------------------------------------------
// K0a: W_pos [F, A] -> transposed split halves g_wp_h/l [A, F].
// ---------------------------------------------------------------------------
__global__ void k0a_split_wpos(const float* __restrict__ Wp) {
    __shared__ float tile[32][33];
    const int a0 = blockIdx.x * 32;
    const int f0 = blockIdx.y * 32;
    const int tx = threadIdx.x & 31;
    const int ty = threadIdx.x >> 5;
#pragma unroll
    for (int i = 0; i < 4; i++) {
        int f = ty + i * 8;
        tile[f][tx] = Wp[(size_t)(f0 + f) * A + a0 + tx];
    }
    __syncthreads();
#pragma unroll
    for (int i = 0; i < 4; i++) {
        int ar = ty + i * 8;
        float x = tile[tx][ar];
        __half hi, lo;
        split_f32(x, hi, lo);
        size_t o = (size_t)(a0 + ar) * F + f0 + tx;
        g_wp_h[o] = hi;
        g_wp_l[o] = lo;
    }
}

// ---------------------------------------------------------------------------
// K0b: pos_features = [wh | pe1 | pe2] -> fp16 plane [M, F].
// ---------------------------------------------------------------------------
__global__ void k0b_split_pf(const float* __restrict__ wh,
                             const float* __restrict__ pe1,
                             const float* __restrict__ pe2) {
    const int m = blockIdx.x;
    const float* s0 = wh  + (size_t)m * H;
    const float* s1 = pe1 + (size_t)m * P;
    const float* s2 = pe2 + (size_t)m * P;
    __half* oh = g_pf_h + (size_t)m * F;
    for (int i = threadIdx.x; i < F / 4; i += 256) {
        int f4 = i * 4;
        float4 x;
        if (f4 < H)            x = *(const float4*)(s0 + f4);
        else if (f4 < H + P)   x = *(const float4*)(s1 + (f4 - H));
        else                   x = *(const float4*)(s2 + (f4 - H - P));
        __half2 hh[2] = {__halves2half2(__float2half_rn(x.x), __float2half_rn(x.y)),
                         __halves2half2(__float2half_rn(x.z), __float2half_rn(x.w))};
        *(uint2*)(oh + f4) = *(uint2*)hh;
    }
}

// ---------------------------------------------------------------------------
// K1: entity gather + latent types + zero accumulators. grid=B, 256 threads.
// ---------------------------------------------------------------------------
__global__ void k1_entity_prep(const float* __restrict__ wh,
                               const int* __restrict__ e1_end,
                               const int* __restrict__ e2_end,
                               const float* __restrict__ te) {
    const int b = blockIdx.x;
    const int tid = threadIdx.x;
    const int lane = tid & 31;
    const int wid = tid >> 5;

    __shared__ float wsum[8][16];
    __shared__ float scores[16];
    __shared__ float alpha[2][T];

    const float* h1 = wh + ((size_t)b * L + e1_end[b]) * H;
    const float* h2 = wh + ((size_t)b * L + e2_end[b]) * H;

    float s[16];
#pragma unroll
    for (int i = 0; i < 16; i++) s[i] = 0.f;
    for (int h = tid; h < H; h += 256) {
        float v1 = h1[h], v2 = h2[h];
#pragma unroll
        for (int t = 0; t < T; t++) {
            float c = te[t * H + h];
            s[t] += v1 * c;
            s[8 + t] += v2 * c;
        }
    }
#pragma unroll
    for (int off = 16; off; off >>= 1)
#pragma unroll
        for (int i = 0; i < 16; i++) s[i] += __shfl_xor_sync(0xffffffffu, s[i], off);
    if (lane == 0)
#pragma unroll
        for (int i = 0; i < 16; i++) wsum[wid][i] = s[i];
    __syncthreads();
    if (tid < 16) {
        float tot = 0.f;
#pragma unroll
        for (int w = 0; w < 8; w++) tot += wsum[w][tid];
        scores[tid] = tot;
    }
    __syncthreads();
    if (tid < 2) {
        const float* sc = scores + tid * 8;
        float m = -1e30f;
#pragma unroll
        for (int i = 0; i < T; i++) m = fmaxf(m, sc[i]);
        float sum = 0.f;
        float e[T];
#pragma unroll
        for (int i = 0; i < T; i++) { e[i] = expf(sc[i] - m); sum += e[i]; }
        float inv = 1.f / sum;
#pragma unroll
        for (int i = 0; i < T; i++) alpha[tid][i] = e[i] * inv;
    }
    __syncthreads();

    float* ef = g_ef + (size_t)b * 4 * H;
    for (int h = tid; h < H; h += 256) {
        float t1 = 0.f, t2 = 0.f;
#pragma unroll
        for (int t = 0; t < T; t++) {
            float c = te[t * H + h];
            t1 += alpha[0][t] * c;
            t2 += alpha[1][t] * c;
        }
        ef[h]         = h1[h];
        ef[H + h]     = t1;
        ef[2 * H + h] = h2[h];
        ef[3 * H + h] = t2;
    }

    g_vu[b * L + tid] = 0.f;
    g_dense_ent[b * A + tid] = 0.f;
    g_dense_ent[b * A + 256 + tid] = 0.f;
}

// ---------------------------------------------------------------------------
// K2 (round-4 best): dense_ent = ef[B,4H] @ W_ent[4H,A]; burst then compute.
// grid = (8 a-tiles of 64, 32 k-splits of 128) = 256 CTAs; 256 threads.
// ---------------------------------------------------------------------------
__global__ void __launch_bounds__(256)
k2_dense_ent(const float* __restrict__ W_ent) {
    __shared__ float sE[64][132];   // [b][k]
    __shared__ float sW[128][68];   // [k][a]

    const int a0 = blockIdx.x * 64;
    const int k0 = blockIdx.y * 128;
    const int tid = threadIdx.x;

#pragma unroll
    for (int j = 0; j < 8; j++) {
        int id = tid + j * 256;
        int r = id >> 5, c4 = (id & 31) * 4;
        CP_ASYNC16(smem_u32(&sE[r][c4]), g_ef + (size_t)r * (4 * H) + k0 + c4);
    }
#pragma unroll
    for (int j = 0; j < 8; j++) {
        int id = tid + j * 256;
        int r = id >> 4, c4 = (id & 15) * 4;
        CP_ASYNC16(smem_u32(&sW[r][c4]), W_ent + (size_t)(k0 + r) * A + a0 + c4);
    }
    CP_COMMIT();
    CP_WAIT0();
    __syncthreads();

    const int tx = tid & 15;
    const int ty = tid >> 4;
    float acc[4][4];
#pragma unroll
    for (int r = 0; r < 4; r++)
#pragma unroll
        for (int c = 0; c < 4; c++) acc[r][c] = 0.f;

#pragma unroll 8
    for (int kt = 0; kt < 128; kt++) {
        float4 w = *(const float4*)&sW[kt][tx * 4];
        float wv[4] = {w.x, w.y, w.z, w.w};
#pragma unroll
        for (int r = 0; r < 4; r++) {
            float e = sE[ty * 4 + r][kt];
#pragma unroll
            for (int c = 0; c < 4; c++) acc[r][c] += e * wv[c];
        }
    }
#pragma unroll
    for (int r = 0; r < 4; r++)
#pragma unroll
        for (int c = 0; c < 4; c++)
            atomicAdd(&g_dense_ent[(ty * 4 + r) * A + a0 + tx * 4 + c], acc[r][c]);
}

// ---------------------------------------------------------------------------
// K3: mma.sync fused GEMM (A fp16; B = hi+lo fp16 split, 2 passes)
//     + tanh + v-dot -> vu.
// CTA 128(M) x 256(N), K=1152 in 18 chunks of 64; 2-stage cp.async pipeline.
// grid = (2, 128); 256 threads = 8 warps (2 M x 4 N), warp tile 64x64.
// ---------------------------------------------------------------------------
#define KT      64
#define PADK    72                      // halves per SMEM row (144 B)
#define A_SZ    (128 * PADK * 2)        // 18432 B (A fp16 plane)
#define B_SZ    (256 * PADK * 2)        // 36864 B per B plane
#define OFF_AH  0
#define OFF_BH  (A_SZ)
#define OFF_BL  (A_SZ + B_SZ)
#define STG_SZ  (A_SZ + 2 * B_SZ)       // 92160 B
#define K3_DSMEM (2 * STG_SZ)           // 184320 B
#define NKCH    (F / KT)                // 18

__global__ void __launch_bounds__(256, 1)
k3_main(const float* __restrict__ v) {
    extern __shared__ char dsm[];
    __shared__ float sv[256];

    const int n0 = blockIdx.x * 256;
    const int m0 = blockIdx.y * 128;
    const int b  = blockIdx.y >> 1;
    const int l0 = (blockIdx.y & 1) * 128;
    const int tid = threadIdx.x;
    const int lane = tid & 31;
    const int wid = tid >> 5;
    const int wm = wid >> 2;     // 0..1, m-offset 64
    const int wn = wid & 3;      // 0..3, n-offset 64

    sv[tid] = v[n0 + tid];
    const uint32_t sbase = smem_u32(dsm);

    // load geometry: 5120 x 16B per stage, 20 per thread
    const int rr   = tid >> 3;          // 0..31
    const int ch8  = (tid & 7) * 8;     // halves
    const int ch16 = (tid & 7) * 16;    // bytes
    const __half* gp0 = g_pf_h + (size_t)m0 * F + ch8;
    const __half* gp2 = g_wp_h + (size_t)n0 * F + ch8;
    const __half* gp3 = g_wp_l + (size_t)n0 * F + ch8;

    auto load_stage = [&](int t, int stg) {
        const int f0 = t * KT;
        const uint32_t sb = sbase + stg * STG_SZ;
#pragma unroll
        for (int j = 0; j < 4; j++) {
            int r = rr + j * 32;
            CP_ASYNC16(sb + OFF_AH + r * (PADK * 2) + ch16, gp0 + (size_t)r * F + f0);
        }
#pragma unroll
        for (int j = 0; j < 8; j++) {
            int r = rr + j * 32;
            CP_ASYNC16(sb + OFF_BH + r * (PADK * 2) + ch16, gp2 + (size_t)r * F + f0);
        }
#pragma unroll
        for (int j = 0; j < 8; j++) {
            int r = rr + j * 32;
            CP_ASYNC16(sb + OFF_BL + r * (PADK * 2) + ch16, gp3 + (size_t)r * F + f0);
        }
    };

    float acc[4][8][4];
#pragma unroll
    for (int mt = 0; mt < 4; mt++)
#pragma unroll
        for (int nt = 0; nt < 8; nt++)
#pragma unroll
            for (int i = 0; i < 4; i++) acc[mt][nt][i] = 0.f;

    load_stage(0, 0); CP_COMMIT();

    for (int t = 0; t < NKCH; t++) {
        const int s = t & 1;
        if (t + 1 < NKCH) { load_stage(t + 1, s ^ 1); CP_COMMIT(); CP_WAIT1(); }
        else              { CP_WAIT0(); }
        __syncthreads();

        const uint32_t st = sbase + s * STG_SZ;
#pragma unroll
        for (int kt = 0; kt < 4; kt++) {
            // A fragments (fp16 only): 4 m16 tiles
            uint32_t ah[4][4];
            const int acol = kt * 16 + ((lane >> 4) << 3);
#pragma unroll
            for (int mt = 0; mt < 4; mt++) {
                int row = wm * 64 + mt * 16 + (lane & 15);
                uint32_t ad = st + row * (PADK * 2) + acol * 2;
                LDSM4(ah[mt][0], ah[mt][1], ah[mt][2], ah[mt][3], ad + OFF_AH);
            }
            // B fragments loaded per 16-row pair
            const int bcol = kt * 16 + ((lane & 8) ? 8 : 0);
            const int brow_in = (lane & 7) + ((lane & 16) ? 8 : 0);
#pragma unroll
            for (int pr = 0; pr < 4; pr++) {
                int row = wn * 64 + pr * 16 + brow_in;
                uint32_t bd = st + row * (PADK * 2) + bcol * 2;
                uint32_t bh0[2], bh1[2], bl0[2], bl1[2];
                uint32_t r0, r1, r2, r3;
                LDSM4(r0, r1, r2, r3, bd + OFF_BH);
                bh0[0] = r0; bh0[1] = r1; bh1[0] = r2; bh1[1] = r3;
                LDSM4(r0, r1, r2, r3, bd + OFF_BL);
                bl0[0] = r0; bl0[1] = r1; bl1[0] = r2; bl1[1] = r3;
#pragma unroll
                for (int mt = 0; mt < 4; mt++) {
                    MMA16816(acc[mt][pr * 2], ah[mt], bh0);
                    MMA16816(acc[mt][pr * 2], ah[mt], bl0);
                    MMA16816(acc[mt][pr * 2 + 1], ah[mt], bh1);
                    MMA16816(acc[mt][pr * 2 + 1], ah[mt], bl1);
                }
            }
        }
        __syncthreads();
    }

    // ---- epilogue: tanh(acc + ent) . v, reduce over quad, atomic into vu ---
    const int halfA = blockIdx.x;               // n0=0 -> 0, n0=256 -> 1
#pragma unroll
    for (int mt = 0; mt < 4; mt++) {
#pragma unroll
        for (int h = 0; h < 2; h++) {
            const int l = l0 + wm * 64 + mt * 16 + (lane >> 2) + h * 8;
            const float e = g_dense_ent[b * A + 2 * l + halfA];
            float part = 0.f;
#pragma unroll
            for (int nt = 0; nt < 8; nt++) {
                int a = wn * 64 + nt * 8 + 2 * (lane & 3);
                part += sv[a]     * tanhf(acc[mt][nt][2 * h]     + e);
                part += sv[a + 1] * tanhf(acc[mt][nt][2 * h + 1] + e);
            }
            part += __shfl_xor_sync(0xffffffffu, part, 1);
            part += __shfl_xor_sync(0xffffffffu, part, 2);
            if ((lane & 3) == 0) atomicAdd(&g_vu[b * L + l], part);
        }
    }
}

// ---------------------------------------------------------------------------
// K4: softmax over L + partial z (split-L x4). grid = (B, 4); 256 threads.
// ---------------------------------------------------------------------------
__global__ void __launch_bounds__(256)
k4_softmax_zp(const float* __restrict__ wh) {
    const int b = blockIdx.x;
    const int lq = blockIdx.y;
    const int tid = threadIdx.x;
    const int lane = tid & 31;
    const int wid = tid >> 5;

    __shared__ float sa[L];
    __shared__ float red[8];

    float vu = g_vu[b * L + tid];

    float m = vu;
#pragma unroll
    for (int off = 16; off; off >>= 1) m = fmaxf(m, __shfl_xor_sync(0xffffffffu, m, off));
    if (lane == 0) red[wid] = m;
    __syncthreads();
    if (tid < 8) {
        float mm = red[tid];
#pragma unroll
        for (int off = 4; off; off >>= 1) mm = fmaxf(mm, __shfl_xor_sync(0xffu, mm, off));
        if (tid == 0) red[0] = mm;
    }
    __syncthreads();
    const float mv = red[0];
    __syncthreads();

    float ex = expf(vu - mv);
    float ssum = ex;
#pragma unroll
    for (int off = 16; off; off >>= 1) ssum += __shfl_xor_sync(0xffffffffu, ssum, off);
    if (lane == 0) red[wid] = ssum;
    __syncthreads();
    if (tid < 8) {
        float ss = red[tid];
#pragma unroll
        for (int off = 4; off; off >>= 1) ss += __shfl_xor_sync(0xffu, ss, off);
        if (tid == 0) red[0] = ss;
    }
    __syncthreads();
    const float inv = 1.f / red[0];
    sa[tid] = ex * inv;
    __syncthreads();

    const int h4 = tid * 4;
    const float* base = wh + ((size_t)b * L + lq * 64) * H + h4;
    float ax = 0.f, ay = 0.f, az = 0.f, aw = 0.f;
#pragma unroll 8
    for (int l2 = 0; l2 < 64; l2++) {
        float4 x = *(const float4*)(base + (size_t)l2 * H);
        float s = sa[lq * 64 + l2];
        ax += s * x.x; ay += s * x.y; az += s * x.z; aw += s * x.w;
    }
    float4 o = {ax, ay, az, aw};
    *(float4*)(&g_zp[lq][b * H + h4]) = o;
}

// ---------------------------------------------------------------------------
// K5: z = sum of 4 partials. 64 blocks x 256 threads, float4 per thread.
// ---------------------------------------------------------------------------
__global__ void k5_combine(float* __restrict__ z) {
    const int i4 = (blockIdx.x * 256 + threadIdx.x) * 4;
    float4 a = *(const float4*)&g_zp[0][i4];
    float4 b = *(const float4*)&g_zp[1][i4];
    float4 c = *(const float4*)&g_zp[2][i4];
    float4 d = *(const float4*)&g_zp[3][i4];
    float4 o = {a.x + b.x + c.x + d.x, a.y + b.y + c.y + d.y,
                a.z + b.z + c.z + d.z, a.w + b.w + c.w + d.w};
    *(float4*)(z + i4) = o;
}

// ---------------------------------------------------------------------------
extern "C" void kernel_launch(void* const* d_in, const int* in_sizes, int n_in,
                              void* d_out, int out_size) {
    const float* wh   = (const float*)d_in[0];
    const float* pe1  = (const float*)d_in[1];
    const float* pe2  = (const float*)d_in[2];
    const int*   e1e  = (const int*)d_in[3];
    const int*   e2e  = (const int*)d_in[4];
    const float* te   = (const float*)d_in[5];
    const float* Wp   = (const float*)d_in[6];
    const float* We   = (const float*)d_in[7];
    const float* v    = (const float*)d_in[8];
    float* z = (float*)d_out;

    cudaFuncSetAttribute(k3_main, cudaFuncAttributeMaxDynamicSharedMemorySize, K3_DSMEM);

    k0a_split_wpos<<<dim3(A / 32, F / 32), 256>>>(Wp);
    k0b_split_pf<<<M_TOT, 256>>>(wh, pe1, pe2);
    k1_entity_prep<<<B, 256>>>(wh, e1e, e2e, te);
    k2_dense_ent<<<dim3(8, 32), 256>>>(We);
    k3_main<<<dim3(2, 128), 256, K3_DSMEM>>>(v);
    k4_softmax_zp<<<dim3(B, 4), 256>>>(wh);
    k5_combine<<<64, 256>>>(z);
}

// round 7
// speedup vs baseline: 6.6254x; 1.3674x over previous
#include <cuda_runtime.h>
#include <cuda_fp16.h>
#include <math.h>
#include <stdint.h>

#define B 64
#define L 256
#define H 1024
#define P 64
#define A 512
#define T 8
#define F (H + 2 * P)   // 1152
#define M_TOT (B * L)   // 16384

// ---------------- scratch (device globals; no allocation allowed) ----------
__device__ float g_ef[B * 4 * H];            // entity_features [B, 4H]
__device__ float g_dense_ent[B * A];         // [B, A]
__device__ float g_vu[B * L];                // [B, L]
__device__ float g_zp[4][B * H];             // z partials (split-L)
__device__ __half g_pf_h[M_TOT * F];         // pos_features fp16 [M, F]
__device__ __half g_wp_h[A * F];             // W_pos^T fp16 [A, F]

// ---------------- helpers --------------------------------------------------
__device__ __forceinline__ uint32_t smem_u32(const void* p) {
    uint32_t a;
    asm("{ .reg .u64 t; cvta.to.shared.u64 t, %1; cvt.u32.u64 %0, t; }" : "=r"(a) : "l"(p));
    return a;
}

#define CP_ASYNC16(smem, gmem) \
    asm volatile("cp.async.cg.shared.global [%0], [%1], 16;" :: "r"(smem), "l"(gmem))
#define CP_COMMIT() asm volatile("cp.async.commit_group;" ::: "memory")
#define CP_WAIT2()  asm volatile("cp.async.wait_group 2;" ::: "memory")
#define CP_WAIT0()  asm volatile("cp.async.wait_group 0;" ::: "memory")

#define LDSM4(r0, r1, r2, r3, addr) \
    asm volatile("ldmatrix.sync.aligned.m8n8.x4.shared.b16 {%0,%1,%2,%3}, [%4];" \
        : "=r"(r0), "=r"(r1), "=r"(r2), "=r"(r3) : "r"(addr))

#define MMA16816(d, a, bb) \
    asm volatile("mma.sync.aligned.m16n8k16.row.col.f32.f16.f16.f32 " \
        "{%0,%1,%2,%3}, {%4,%5,%6,%7}, {%8,%9}, {%0,%1,%2,%3};" \
        : "+f"((d)[0]), "+f"((d)[1]), "+f"((d)[2]), "+f"((d)[3]) \
        : "r"((a)[0]), "r"((a)[1]), "r"((a)[2]), "r"((a)[3]), "r"((bb)[0]), "r"((bb)[1]))

// ---------------------------------------------------------------------------
// K0a: W_pos [F, A] -> transposed fp16 g_wp_h [A, F].
// ---------------------------------------------------------------------------
__global__ void k0a_split_wpos(const float* __restrict__ Wp) {
    __shared__ float tile[32][33];
    const int a0 = blockIdx.x * 32;
    const int f0 = blockIdx.y * 32;
    const int tx = threadIdx.x & 31;
    const int ty = threadIdx.x >> 5;
#pragma unroll
    for (int i = 0; i < 4; i++) {
        int f = ty + i * 8;
        tile[f][tx] = Wp[(size_t)(f0 + f) * A + a0 + tx];
    }
    __syncthreads();
#pragma unroll
    for (int i = 0; i < 4; i++) {
        int ar = ty + i * 8;
        g_wp_h[(size_t)(a0 + ar) * F + f0 + tx] = __float2half_rn(tile[tx][ar]);
    }
}

// ---------------------------------------------------------------------------
// K0b: pos_features = [wh | pe1 | pe2] -> fp16 plane [M, F].
// ---------------------------------------------------------------------------
__global__ void k0b_split_pf(const float* __restrict__ wh,
                             const float* __restrict__ pe1,
                             const float* __restrict__ pe2) {
    const int m = blockIdx.x;
    const float* s0 = wh  + (size_t)m * H;
    const float* s1 = pe1 + (size_t)m * P;
    const float* s2 = pe2 + (size_t)m * P;
    __half* oh = g_pf_h + (size_t)m * F;
    for (int i = threadIdx.x; i < F / 4; i += 256) {
        int f4 = i * 4;
        float4 x;
        if (f4 < H)            x = *(const float4*)(s0 + f4);
        else if (f4 < H + P)   x = *(const float4*)(s1 + (f4 - H));
        else                   x = *(const float4*)(s2 + (f4 - H - P));
        __half2 hh[2] = {__halves2half2(__float2half_rn(x.x), __float2half_rn(x.y)),
                         __halves2half2(__float2half_rn(x.z), __float2half_rn(x.w))};
        *(uint2*)(oh + f4) = *(uint2*)hh;
    }
}

// ---------------------------------------------------------------------------
// K1: entity gather + latent types + zero accumulators. grid=B, 256 threads.
// ---------------------------------------------------------------------------
__global__ void k1_entity_prep(const float* __restrict__ wh,
                               const int* __restrict__ e1_end,
                               const int* __restrict__ e2_end,
                               const float* __restrict__ te) {
    const int b = blockIdx.x;
    const int tid = threadIdx.x;
    const int lane = tid & 31;
    const int wid = tid >> 5;

    __shared__ float wsum[8][16];
    __shared__ float scores[16];
    __shared__ float alpha[2][T];

    const float* h1 = wh + ((size_t)b * L + e1_end[b]) * H;
    const float* h2 = wh + ((size_t)b * L + e2_end[b]) * H;

    float s[16];
#pragma unroll
    for (int i = 0; i < 16; i++) s[i] = 0.f;
    for (int h = tid; h < H; h += 256) {
        float v1 = h1[h], v2 = h2[h];
#pragma unroll
        for (int t = 0; t < T; t++) {
            float c = te[t * H + h];
            s[t] += v1 * c;
            s[8 + t] += v2 * c;
        }
    }
#pragma unroll
    for (int off = 16; off; off >>= 1)
#pragma unroll
        for (int i = 0; i < 16; i++) s[i] += __shfl_xor_sync(0xffffffffu, s[i], off);
    if (lane == 0)
#pragma unroll
        for (int i = 0; i < 16; i++) wsum[wid][i] = s[i];
    __syncthreads();
    if (tid < 16) {
        float tot = 0.f;
#pragma unroll
        for (int w = 0; w < 8; w++) tot += wsum[w][tid];
        scores[tid] = tot;
    }
    __syncthreads();
    if (tid < 2) {
        const float* sc = scores + tid * 8;
        float m = -1e30f;
#pragma unroll
        for (int i = 0; i < T; i++) m = fmaxf(m, sc[i]);
        float sum = 0.f;
        float e[T];
#pragma unroll
        for (int i = 0; i < T; i++) { e[i] = expf(sc[i] - m); sum += e[i]; }
        float inv = 1.f / sum;
#pragma unroll
        for (int i = 0; i < T; i++) alpha[tid][i] = e[i] * inv;
    }
    __syncthreads();

    float* ef = g_ef + (size_t)b * 4 * H;
    for (int h = tid; h < H; h += 256) {
        float t1 = 0.f, t2 = 0.f;
#pragma unroll
        for (int t = 0; t < T; t++) {
            float c = te[t * H + h];
            t1 += alpha[0][t] * c;
            t2 += alpha[1][t] * c;
        }
        ef[h]         = h1[h];
        ef[H + h]     = t1;
        ef[2 * H + h] = h2[h];
        ef[3 * H + h] = t2;
    }

    g_vu[b * L + tid] = 0.f;
    g_dense_ent[b * A + tid] = 0.f;
    g_dense_ent[b * A + 256 + tid] = 0.f;
}

// ---------------------------------------------------------------------------
// K2: dense_ent = ef[B,4H] @ W_ent[4H,A]; burst then compute.
// grid = (8 a-tiles of 64, 32 k-splits of 128) = 256 CTAs; 256 threads.
// ---------------------------------------------------------------------------
__global__ void __launch_bounds__(256)
k2_dense_ent(const float* __restrict__ W_ent) {
    __shared__ float sE[64][132];   // [b][k]
    __shared__ float sW[128][68];   // [k][a]

    const int a0 = blockIdx.x * 64;
    const int k0 = blockIdx.y * 128;
    const int tid = threadIdx.x;

#pragma unroll
    for (int j = 0; j < 8; j++) {
        int id = tid + j * 256;
        int r = id >> 5, c4 = (id & 31) * 4;
        CP_ASYNC16(smem_u32(&sE[r][c4]), g_ef + (size_t)r * (4 * H) + k0 + c4);
    }
#pragma unroll
    for (int j = 0; j < 8; j++) {
        int id = tid + j * 256;
        int r = id >> 4, c4 = (id & 15) * 4;
        CP_ASYNC16(smem_u32(&sW[r][c4]), W_ent + (size_t)(k0 + r) * A + a0 + c4);
    }
    CP_COMMIT();
    CP_WAIT0();
    __syncthreads();

    const int tx = tid & 15;
    const int ty = tid >> 4;
    float acc[4][4];
#pragma unroll
    for (int r = 0; r < 4; r++)
#pragma unroll
        for (int c = 0; c < 4; c++) acc[r][c] = 0.f;

#pragma unroll 8
    for (int kt = 0; kt < 128; kt++) {
        float4 w = *(const float4*)&sW[kt][tx * 4];
        float wv[4] = {w.x, w.y, w.z, w.w};
#pragma unroll
        for (int r = 0; r < 4; r++) {
            float e = sE[ty * 4 + r][kt];
#pragma unroll
            for (int c = 0; c < 4; c++) acc[r][c] += e * wv[c];
        }
    }
#pragma unroll
    for (int r = 0; r < 4; r++)
#pragma unroll
        for (int c = 0; c < 4; c++)
            atomicAdd(&g_dense_ent[(ty * 4 + r) * A + a0 + tx * 4 + c], acc[r][c]);
}

// ---------------------------------------------------------------------------
// K3: mma.sync fused GEMM (single-pass fp16 x fp16, fp32 accum)
//     + tanh + v-dot -> vu.
// CTA 128(M) x 256(N), K=1152 in 18 chunks of 64; 3-stage cp.async pipeline.
// grid = (2, 128); 256 threads = 8 warps (2 M x 4 N), warp tile 64x64.
// ---------------------------------------------------------------------------
#define KT      64
#define PADK    72                      // halves per SMEM row (144 B)
#define A_SZ    (128 * PADK * 2)        // 18432 B
#define B_SZ    (256 * PADK * 2)        // 36864 B
#define OFF_A   0
#define OFF_B   (A_SZ)
#define STG_SZ  (A_SZ + B_SZ)           // 55296 B
#define NSTG    3
#define K3_DSMEM (NSTG * STG_SZ)        // 165888 B
#define NKCH    (F / KT)                // 18

__global__ void __launch_bounds__(256, 1)
k3_main(const float* __restrict__ v) {
    extern __shared__ char dsm[];
    __shared__ float sv[256];

    const int n0 = blockIdx.x * 256;
    const int m0 = blockIdx.y * 128;
    const int b  = blockIdx.y >> 1;
    const int l0 = (blockIdx.y & 1) * 128;
    const int tid = threadIdx.x;
    const int lane = tid & 31;
    const int wid = tid >> 5;
    const int wm = wid >> 2;     // 0..1, m-offset 64
    const int wn = wid & 3;      // 0..3, n-offset 64

    sv[tid] = v[n0 + tid];
    const uint32_t sbase = smem_u32(dsm);

    // load geometry: 3072 x 16B per stage, 12 per thread
    const int rr   = tid >> 3;          // 0..31
    const int ch8  = (tid & 7) * 8;     // halves
    const int ch16 = (tid & 7) * 16;    // bytes
    const __half* gp0 = g_pf_h + (size_t)m0 * F + ch8;
    const __half* gp2 = g_wp_h + (size_t)n0 * F + ch8;

    auto load_stage = [&](int t, int stg) {
        const int f0 = t * KT;
        const uint32_t sb = sbase + stg * STG_SZ;
#pragma unroll
        for (int j = 0; j < 4; j++) {
            int r = rr + j * 32;
            CP_ASYNC16(sb + OFF_A + r * (PADK * 2) + ch16, gp0 + (size_t)r * F + f0);
        }
#pragma unroll
        for (int j = 0; j < 8; j++) {
            int r = rr + j * 32;
            CP_ASYNC16(sb + OFF_B + r * (PADK * 2) + ch16, gp2 + (size_t)r * F + f0);
        }
    };

    float acc[4][8][4];
#pragma unroll
    for (int mt = 0; mt < 4; mt++)
#pragma unroll
        for (int nt = 0; nt < 8; nt++)
#pragma unroll
            for (int i = 0; i < 4; i++) acc[mt][nt][i] = 0.f;

    load_stage(0, 0); CP_COMMIT();
    load_stage(1, 1); CP_COMMIT();

    for (int t = 0; t < NKCH; t++) {
        const int s = t % NSTG;
        if (t + 2 < NKCH) { load_stage(t + 2, (t + 2) % NSTG); CP_COMMIT(); CP_WAIT2(); }
        else              { CP_WAIT0(); }
        __syncthreads();

        const uint32_t st = sbase + s * STG_SZ;
#pragma unroll
        for (int kt = 0; kt < 4; kt++) {
            // A fragments: 4 m16 tiles
            uint32_t ah[4][4];
            const int acol = kt * 16 + ((lane >> 4) << 3);
#pragma unroll
            for (int mt = 0; mt < 4; mt++) {
                int row = wm * 64 + mt * 16 + (lane & 15);
                uint32_t ad = st + OFF_A + row * (PADK * 2) + acol * 2;
                LDSM4(ah[mt][0], ah[mt][1], ah[mt][2], ah[mt][3], ad);
            }
            // B fragments per 16-row pair
            const int bcol = kt * 16 + ((lane & 8) ? 8 : 0);
            const int brow_in = (lane & 7) + ((lane & 16) ? 8 : 0);
#pragma unroll
            for (int pr = 0; pr < 4; pr++) {
                int row = wn * 64 + pr * 16 + brow_in;
                uint32_t bd = st + OFF_B + row * (PADK * 2) + bcol * 2;
                uint32_t b0[2], b1[2];
                uint32_t r0, r1, r2, r3;
                LDSM4(r0, r1, r2, r3, bd);
                b0[0] = r0; b0[1] = r1; b1[0] = r2; b1[1] = r3;
#pragma unroll
                for (int mt = 0; mt < 4; mt++) {
                    MMA16816(acc[mt][pr * 2],     ah[mt], b0);
                    MMA16816(acc[mt][pr * 2 + 1], ah[mt], b1);
                }
            }
        }
        __syncthreads();
    }

    // ---- epilogue: tanh(acc + ent) . v, reduce over quad, atomic into vu ---
    const int halfA = blockIdx.x;               // n0=0 -> 0, n0=256 -> 1
#pragma unroll
    for (int mt = 0; mt < 4; mt++) {
#pragma unroll
        for (int h = 0; h < 2; h++) {
            const int l = l0 + wm * 64 + mt * 16 + (lane >> 2) + h * 8;
            const float e = g_dense_ent[b * A + 2 * l + halfA];
            float part = 0.f;
#pragma unroll
            for (int nt = 0; nt < 8; nt++) {
                int a = wn * 64 + nt * 8 + 2 * (lane & 3);
                part += sv[a]     * tanhf(acc[mt][nt][2 * h]     + e);
                part += sv[a + 1] * tanhf(acc[mt][nt][2 * h + 1] + e);
            }
            part += __shfl_xor_sync(0xffffffffu, part, 1);
            part += __shfl_xor_sync(0xffffffffu, part, 2);
            if ((lane & 3) == 0) atomicAdd(&g_vu[b * L + l], part);
        }
    }
}

// ---------------------------------------------------------------------------
// K4: softmax over L + partial z (split-L x4). grid = (B, 4); 256 threads.
// ---------------------------------------------------------------------------
__global__ void __launch_bounds__(256)
k4_softmax_zp(const float* __restrict__ wh) {
    const int b = blockIdx.x;
    const int lq = blockIdx.y;
    const int tid = threadIdx.x;
    const int lane = tid & 31;
    const int wid = tid >> 5;

    __shared__ float sa[L];
    __shared__ float red[8];

    float vu = g_vu[b * L + tid];

    float m = vu;
#pragma unroll
    for (int off = 16; off; off >>= 1) m = fmaxf(m, __shfl_xor_sync(0xffffffffu, m, off));
    if (lane == 0) red[wid] = m;
    __syncthreads();
    if (tid < 8) {
        float mm = red[tid];
#pragma unroll
        for (int off = 4; off; off >>= 1) mm = fmaxf(mm, __shfl_xor_sync(0xffu, mm, off));
        if (tid == 0) red[0] = mm;
    }
    __syncthreads();
    const float mv = red[0];
    __syncthreads();

    float ex = expf(vu - mv);
    float ssum = ex;
#pragma unroll
    for (int off = 16; off; off >>= 1) ssum += __shfl_xor_sync(0xffffffffu, ssum, off);
    if (lane == 0) red[wid] = ssum;
    __syncthreads();
    if (tid < 8) {
        float ss = red[tid];
#pragma unroll
        for (int off = 4; off; off >>= 1) ss += __shfl_xor_sync(0xffu, ss, off);
        if (tid == 0) red[0] = ss;
    }
    __syncthreads();
    const float inv = 1.f / red[0];
    sa[tid] = ex * inv;
    __syncthreads();

    const int h4 = tid * 4;
    const float* base = wh + ((size_t)b * L + lq * 64) * H + h4;
    float ax = 0.f, ay = 0.f, az = 0.f, aw = 0.f;
#pragma unroll 8
    for (int l2 = 0; l2 < 64; l2++) {
        float4 x = *(const float4*)(base + (size_t)l2 * H);
        float s = sa[lq * 64 + l2];
        ax += s * x.x; ay += s * x.y; az += s * x.z; aw += s * x.w;
    }
    float4 o = {ax, ay, az, aw};
    *(float4*)(&g_zp[lq][b * H + h4]) = o;
}

// ---------------------------------------------------------------------------
// K5: z = sum of 4 partials. 64 blocks x 256 threads, float4 per thread.
// ---------------------------------------------------------------------------
__global__ void k5_combine(float* __restrict__ z) {
    const int i4 = (blockIdx.x * 256 + threadIdx.x) * 4;
    float4 a = *(const float4*)&g_zp[0][i4];
    float4 b = *(const float4*)&g_zp[1][i4];
    float4 c = *(const float4*)&g_zp[2][i4];
    float4 d = *(const float4*)&g_zp[3][i4];
    float4 o = {a.x + b.x + c.x + d.x, a.y + b.y + c.y + d.y,
                a.z + b.z + c.z + d.z, a.w + b.w + c.w + d.w};
    *(float4*)(z + i4) = o;
}

// ---------------------------------------------------------------------------
extern "C" void kernel_launch(void* const* d_in, const int* in_sizes, int n_in,
                              void* d_out, int out_size) {
    const float* wh   = (const float*)d_in[0];
    const float* pe1  = (const float*)d_in[1];
    const float* pe2  = (const float*)d_in[2];
    const int*   e1e  = (const int*)d_in[3];
    const int*   e2e  = (const int*)d_in[4];
    const float* te   = (const float*)d_in[5];
    const float* Wp   = (const float*)d_in[6];
    const float* We   = (const float*)d_in[7];
    const float* v    = (const float*)d_in[8];
    float* z = (float*)d_out;

    cudaFuncSetAttribute(k3_main, cudaFuncAttributeMaxDynamicSharedMemorySize, K3_DSMEM);

    k0a_split_wpos<<<dim3(A / 32, F / 32), 256>>>(Wp);
    k0b_split_pf<<<M_TOT, 256>>>(wh, pe1, pe2);
    k1_entity_prep<<<B, 256>>>(wh, e1e, e2e, te);
    k2_dense_ent<<<dim3(8, 32), 256>>>(We);
    k3_main<<<dim3(2, 128), 256, K3_DSMEM>>>(v);
    k4_softmax_zp<<<dim3(B, 4), 256>>>(wh);
    k5_combine<<<64, 256>>>(z);
}

// round 8
// speedup vs baseline: 7.1742x; 1.0828x over previous
#include <cuda_runtime.h>
#include <cuda_fp16.h>
#include <math.h>
#include <stdint.h>

#define B 64
#define L 256
#define H 1024
#define P 64
#define A 512
#define T 8
#define F (H + 2 * P)   // 1152
#define M_TOT (B * L)   // 16384

// ---------------- scratch (device globals; no allocation allowed) ----------
__device__ float g_ef[B * 4 * H];            // entity_features [B, 4H]
__device__ float g_dense_ent[B * A];         // [B, A]
__device__ float g_vu[B * L];                // [B, L]
__device__ float g_zp[4][B * H];             // z partials (split-L)
__device__ __half g_pf_h[M_TOT * F];         // pos_features fp16 [M, F]
__device__ __half g_wp_h[A * F];             // W_pos^T fp16 [A, F]

// ---------------- helpers --------------------------------------------------
__device__ __forceinline__ uint32_t smem_u32(const void* p) {
    uint32_t a;
    asm("{ .reg .u64 t; cvta.to.shared.u64 t, %1; cvt.u32.u64 %0, t; }" : "=r"(a) : "l"(p));
    return a;
}

#define CP_ASYNC16(smem, gmem) \
    asm volatile("cp.async.cg.shared.global [%0], [%1], 16;" :: "r"(smem), "l"(gmem))
#define CP_COMMIT() asm volatile("cp.async.commit_group;" ::: "memory")
#define CP_WAIT1()  asm volatile("cp.async.wait_group 1;" ::: "memory")
#define CP_WAIT0()  asm volatile("cp.async.wait_group 0;" ::: "memory")

#define LDSM4(r0, r1, r2, r3, addr) \
    asm volatile("ldmatrix.sync.aligned.m8n8.x4.shared.b16 {%0,%1,%2,%3}, [%4];" \
        : "=r"(r0), "=r"(r1), "=r"(r2), "=r"(r3) : "r"(addr))

#define MMA16816(d, a, bb) \
    asm volatile("mma.sync.aligned.m16n8k16.row.col.f32.f16.f16.f32 " \
        "{%0,%1,%2,%3}, {%4,%5,%6,%7}, {%8,%9}, {%0,%1,%2,%3};" \
        : "+f"((d)[0]), "+f"((d)[1]), "+f"((d)[2]), "+f"((d)[3]) \
        : "r"((a)[0]), "r"((a)[1]), "r"((a)[2]), "r"((a)[3]), "r"((bb)[0]), "r"((bb)[1]))

// ---------------------------------------------------------------------------
// K_PREP: fused k0b (pf->fp16), k0a (W_pos^T->fp16), k1 (entity prep).
// grid = 16384 + 576 + 64 = 17024 CTAs; 256 threads.
//   bx <  16384            : pf conversion for row m = bx
//   16384 <= bx < 16960    : W_pos transpose tile
//   bx >= 16960            : entity prep for batch b = bx - 16960
// ---------------------------------------------------------------------------
#define NB_PF  M_TOT
#define NB_WP  ((A / 32) * (F / 32))   // 576
#define NB_ENT B

__global__ void __launch_bounds__(256)
k_prep(const float* __restrict__ wh,
       const float* __restrict__ pe1,
       const float* __restrict__ pe2,
       const float* __restrict__ Wp,
       const int* __restrict__ e1_end,
       const int* __restrict__ e2_end,
       const float* __restrict__ te) {
    const int bx = blockIdx.x;
    const int tid = threadIdx.x;

    if (bx < NB_PF) {
        // ---- pos_features -> fp16 plane [M, F] ----
        const int m = bx;
        const float* s0 = wh  + (size_t)m * H;
        const float* s1 = pe1 + (size_t)m * P;
        const float* s2 = pe2 + (size_t)m * P;
        __half* oh = g_pf_h + (size_t)m * F;
        for (int i = tid; i < F / 4; i += 256) {
            int f4 = i * 4;
            float4 x;
            if (f4 < H)            x = *(const float4*)(s0 + f4);
            else if (f4 < H + P)   x = *(const float4*)(s1 + (f4 - H));
            else                   x = *(const float4*)(s2 + (f4 - H - P));
            __half2 hh[2] = {__halves2half2(__float2half_rn(x.x), __float2half_rn(x.y)),
                             __halves2half2(__float2half_rn(x.z), __float2half_rn(x.w))};
            *(uint2*)(oh + f4) = *(uint2*)hh;
        }
        return;
    }

    if (bx < NB_PF + NB_WP) {
        // ---- W_pos [F, A] -> transposed fp16 g_wp_h [A, F] ----
        __shared__ float tile[32][33];
        const int t0 = bx - NB_PF;
        const int a0 = (t0 & 15) * 32;          // 16 a-tiles
        const int f0 = (t0 >> 4) * 32;          // 36 f-tiles
        const int tx = tid & 31;
        const int ty = tid >> 5;
#pragma unroll
        for (int i = 0; i < 4; i++) {
            int f = ty + i * 8;
            tile[f][tx] = Wp[(size_t)(f0 + f) * A + a0 + tx];
        }
        __syncthreads();
#pragma unroll
        for (int i = 0; i < 4; i++) {
            int ar = ty + i * 8;
            g_wp_h[(size_t)(a0 + ar) * F + f0 + tx] = __float2half_rn(tile[tx][ar]);
        }
        return;
    }

    // ---- entity prep for batch b ----
    {
        const int b = bx - NB_PF - NB_WP;
        const int lane = tid & 31;
        const int wid = tid >> 5;

        __shared__ float wsum[8][16];
        __shared__ float scores[16];
        __shared__ float alpha[2][T];

        const float* h1 = wh + ((size_t)b * L + e1_end[b]) * H;
        const float* h2 = wh + ((size_t)b * L + e2_end[b]) * H;

        float s[16];
#pragma unroll
        for (int i = 0; i < 16; i++) s[i] = 0.f;
        for (int h = tid; h < H; h += 256) {
            float v1 = h1[h], v2 = h2[h];
#pragma unroll
            for (int t = 0; t < T; t++) {
                float c = te[t * H + h];
                s[t] += v1 * c;
                s[8 + t] += v2 * c;
            }
        }
#pragma unroll
        for (int off = 16; off; off >>= 1)
#pragma unroll
            for (int i = 0; i < 16; i++) s[i] += __shfl_xor_sync(0xffffffffu, s[i], off);
        if (lane == 0)
#pragma unroll
            for (int i = 0; i < 16; i++) wsum[wid][i] = s[i];
        __syncthreads();
        if (tid < 16) {
            float tot = 0.f;
#pragma unroll
            for (int w = 0; w < 8; w++) tot += wsum[w][tid];
            scores[tid] = tot;
        }
        __syncthreads();
        if (tid < 2) {
            const float* sc = scores + tid * 8;
            float m = -1e30f;
#pragma unroll
            for (int i = 0; i < T; i++) m = fmaxf(m, sc[i]);
            float sum = 0.f;
            float e[T];
#pragma unroll
            for (int i = 0; i < T; i++) { e[i] = expf(sc[i] - m); sum += e[i]; }
            float inv = 1.f / sum;
#pragma unroll
            for (int i = 0; i < T; i++) alpha[tid][i] = e[i] * inv;
        }
        __syncthreads();

        float* ef = g_ef + (size_t)b * 4 * H;
        for (int h = tid; h < H; h += 256) {
            float t1 = 0.f, t2 = 0.f;
#pragma unroll
            for (int t = 0; t < T; t++) {
                float c = te[t * H + h];
                t1 += alpha[0][t] * c;
                t2 += alpha[1][t] * c;
            }
            ef[h]         = h1[h];
            ef[H + h]     = t1;
            ef[2 * H + h] = h2[h];
            ef[3 * H + h] = t2;
        }

        g_vu[b * L + tid] = 0.f;
        g_dense_ent[b * A + tid] = 0.f;
        g_dense_ent[b * A + 256 + tid] = 0.f;
    }
}

// ---------------------------------------------------------------------------
// K2: dense_ent = ef[B,4H] @ W_ent[4H,A]; burst then compute.
// grid = (8 a-tiles of 64, 32 k-splits of 128) = 256 CTAs; 256 threads.
// ---------------------------------------------------------------------------
__global__ void __launch_bounds__(256)
k2_dense_ent(const float* __restrict__ W_ent) {
    __shared__ float sE[64][132];   // [b][k]
    __shared__ float sW[128][68];   // [k][a]

    const int a0 = blockIdx.x * 64;
    const int k0 = blockIdx.y * 128;
    const int tid = threadIdx.x;

#pragma unroll
    for (int j = 0; j < 8; j++) {
        int id = tid + j * 256;
        int r = id >> 5, c4 = (id & 31) * 4;
        CP_ASYNC16(smem_u32(&sE[r][c4]), g_ef + (size_t)r * (4 * H) + k0 + c4);
    }
#pragma unroll
    for (int j = 0; j < 8; j++) {
        int id = tid + j * 256;
        int r = id >> 4, c4 = (id & 15) * 4;
        CP_ASYNC16(smem_u32(&sW[r][c4]), W_ent + (size_t)(k0 + r) * A + a0 + c4);
    }
    CP_COMMIT();
    CP_WAIT0();
    __syncthreads();

    const int tx = tid & 15;
    const int ty = tid >> 4;
    float acc[4][4];
#pragma unroll
    for (int r = 0; r < 4; r++)
#pragma unroll
        for (int c = 0; c < 4; c++) acc[r][c] = 0.f;

#pragma unroll 8
    for (int kt = 0; kt < 128; kt++) {
        float4 w = *(const float4*)&sW[kt][tx * 4];
        float wv[4] = {w.x, w.y, w.z, w.w};
#pragma unroll
        for (int r = 0; r < 4; r++) {
            float e = sE[ty * 4 + r][kt];
#pragma unroll
            for (int c = 0; c < 4; c++) acc[r][c] += e * wv[c];
        }
    }
#pragma unroll
    for (int r = 0; r < 4; r++)
#pragma unroll
        for (int c = 0; c < 4; c++)
            atomicAdd(&g_dense_ent[(ty * 4 + r) * A + a0 + tx * 4 + c], acc[r][c]);
}

// ---------------------------------------------------------------------------
// K3: mma.sync fused GEMM (fp16 x fp16, fp32 accum) + tanh + v-dot -> vu.
// CTA 128(M) x 256(N), K=1152 in 18 chunks of 64; 3-stage cp.async pipeline,
// ONE __syncthreads per mainloop iteration.
// grid = (2, 128); 256 threads = 8 warps (2 M x 4 N), warp tile 64x64.
// ---------------------------------------------------------------------------
#define KT      64
#define PADK    72                      // halves per SMEM row (144 B)
#define A_SZ    (128 * PADK * 2)        // 18432 B
#define B_SZ    (256 * PADK * 2)        // 36864 B
#define OFF_A   0
#define OFF_B   (A_SZ)
#define STG_SZ  (A_SZ + B_SZ)           // 55296 B
#define NSTG    3
#define K3_DSMEM (NSTG * STG_SZ)        // 165888 B
#define NKCH    (F / KT)                // 18

__global__ void __launch_bounds__(256, 1)
k3_main(const float* __restrict__ v) {
    extern __shared__ char dsm[];
    __shared__ float sv[256];

    const int n0 = blockIdx.x * 256;
    const int m0 = blockIdx.y * 128;
    const int b  = blockIdx.y >> 1;
    const int l0 = (blockIdx.y & 1) * 128;
    const int tid = threadIdx.x;
    const int lane = tid & 31;
    const int wid = tid >> 5;
    const int wm = wid >> 2;     // 0..1, m-offset 64
    const int wn = wid & 3;      // 0..3, n-offset 64

    sv[tid] = v[n0 + tid];
    const uint32_t sbase = smem_u32(dsm);

    const int rr   = tid >> 3;          // 0..31
    const int ch8  = (tid & 7) * 8;     // halves
    const int ch16 = (tid & 7) * 16;    // bytes
    const __half* gp0 = g_pf_h + (size_t)m0 * F + ch8;
    const __half* gp2 = g_wp_h + (size_t)n0 * F + ch8;

    auto load_stage = [&](int t, int stg) {
        const int f0 = t * KT;
        const uint32_t sb = sbase + stg * STG_SZ;
#pragma unroll
        for (int j = 0; j < 4; j++) {
            int r = rr + j * 32;
            CP_ASYNC16(sb + OFF_A + r * (PADK * 2) + ch16, gp0 + (size_t)r * F + f0);
        }
#pragma unroll
        for (int j = 0; j < 8; j++) {
            int r = rr + j * 32;
            CP_ASYNC16(sb + OFF_B + r * (PADK * 2) + ch16, gp2 + (size_t)r * F + f0);
        }
    };

    float acc[4][8][4];
#pragma unroll
    for (int mt = 0; mt < 4; mt++)
#pragma unroll
        for (int nt = 0; nt < 8; nt++)
#pragma unroll
            for (int i = 0; i < 4; i++) acc[mt][nt][i] = 0.f;

    load_stage(0, 0); CP_COMMIT();
    load_stage(1, 1); CP_COMMIT();

    for (int t = 0; t < NKCH; t++) {
        const int s = t % NSTG;
        // stage t ready (own groups), then barrier: after this, stage (t-1)%3
        // is no longer read by any warp -> safe to overwrite later this iter.
        if (t + 1 < NKCH) CP_WAIT1(); else CP_WAIT0();
        __syncthreads();

        const uint32_t st = sbase + s * STG_SZ;
#pragma unroll
        for (int kt = 0; kt < 4; kt++) {
            uint32_t ah[4][4];
            const int acol = kt * 16 + ((lane >> 4) << 3);
#pragma unroll
            for (int mt = 0; mt < 4; mt++) {
                int row = wm * 64 + mt * 16 + (lane & 15);
                uint32_t ad = st + OFF_A + row * (PADK * 2) + acol * 2;
                LDSM4(ah[mt][0], ah[mt][1], ah[mt][2], ah[mt][3], ad);
            }
            const int bcol = kt * 16 + ((lane & 8) ? 8 : 0);
            const int brow_in = (lane & 7) + ((lane & 16) ? 8 : 0);
#pragma unroll
            for (int pr = 0; pr < 4; pr++) {
                int row = wn * 64 + pr * 16 + brow_in;
                uint32_t bd = st + OFF_B + row * (PADK * 2) + bcol * 2;
                uint32_t b0[2], b1[2];
                uint32_t r0, r1, r2, r3;
                LDSM4(r0, r1, r2, r3, bd);
                b0[0] = r0; b0[1] = r1; b1[0] = r2; b1[1] = r3;
#pragma unroll
                for (int mt = 0; mt < 4; mt++) {
                    MMA16816(acc[mt][pr * 2],     ah[mt], b0);
                    MMA16816(acc[mt][pr * 2 + 1], ah[mt], b1);
                }
            }
        }

        // issue next prefetch AFTER this warp's compute (writes stage (t-1)%3)
        if (t + 2 < NKCH) { load_stage(t + 2, (t + 2) % NSTG); CP_COMMIT(); }
    }

    // ---- epilogue: tanh(acc + ent) . v, reduce over quad, atomic into vu ---
    const int halfA = blockIdx.x;               // n0=0 -> 0, n0=256 -> 1
#pragma unroll
    for (int mt = 0; mt < 4; mt++) {
#pragma unroll
        for (int h = 0; h < 2; h++) {
            const int l = l0 + wm * 64 + mt * 16 + (lane >> 2) + h * 8;
            const float e = g_dense_ent[b * A + 2 * l + halfA];
            float part = 0.f;
#pragma unroll
            for (int nt = 0; nt < 8; nt++) {
                int a = wn * 64 + nt * 8 + 2 * (lane & 3);
                part += sv[a]     * tanhf(acc[mt][nt][2 * h]     + e);
                part += sv[a + 1] * tanhf(acc[mt][nt][2 * h + 1] + e);
            }
            part += __shfl_xor_sync(0xffffffffu, part, 1);
            part += __shfl_xor_sync(0xffffffffu, part, 2);
            if ((lane & 3) == 0) atomicAdd(&g_vu[b * L + l], part);
        }
    }
}

// ---------------------------------------------------------------------------
// K4: softmax over L + partial z from fp16 pf plane. grid=(B,4); 256 threads.
// ---------------------------------------------------------------------------
__global__ void __launch_bounds__(256)
k4_softmax_zp() {
    const int b = blockIdx.x;
    const int lq = blockIdx.y;
    const int tid = threadIdx.x;
    const int lane = tid & 31;
    const int wid = tid >> 5;

    __shared__ float sa[L];
    __shared__ float red[8];

    float vu = g_vu[b * L + tid];

    float m = vu;
#pragma unroll
    for (int off = 16; off; off >>= 1) m = fmaxf(m, __shfl_xor_sync(0xffffffffu, m, off));
    if (lane == 0) red[wid] = m;
    __syncthreads();
    if (tid < 8) {
        float mm = red[tid];
#pragma unroll
        for (int off = 4; off; off >>= 1) mm = fmaxf(mm, __shfl_xor_sync(0xffu, mm, off));
        if (tid == 0) red[0] = mm;
    }
    __syncthreads();
    const float mv = red[0];
    __syncthreads();

    float ex = expf(vu - mv);
    float ssum = ex;
#pragma unroll
    for (int off = 16; off; off >>= 1) ssum += __shfl_xor_sync(0xffffffffu, ssum, off);
    if (lane == 0) red[wid] = ssum;
    __syncthreads();
    if (tid < 8) {
        float ss = red[tid];
#pragma unroll
        for (int off = 4; off; off >>= 1) ss += __shfl_xor_sync(0xffu, ss, off);
        if (tid == 0) red[0] = ss;
    }
    __syncthreads();
    const float inv = 1.f / red[0];
    sa[tid] = ex * inv;
    __syncthreads();

    // z partial from fp16 wh (= first H columns of g_pf_h)
    const int h4 = tid * 4;
    const __half* base = g_pf_h + ((size_t)b * L + lq * 64) * F + h4;
    float ax = 0.f, ay = 0.f, az = 0.f, aw = 0.f;
#pragma unroll 8
    for (int l2 = 0; l2 < 64; l2++) {
        uint2 raw = *(const uint2*)(base + (size_t)l2 * F);
        __half2 p0 = *(__half2*)&raw.x;
        __half2 p1 = *(__half2*)&raw.y;
        float2 f0 = __half22float2(p0);
        float2 f1 = __half22float2(p1);
        float s = sa[lq * 64 + l2];
        ax += s * f0.x; ay += s * f0.y; az += s * f1.x; aw += s * f1.y;
    }
    float4 o = {ax, ay, az, aw};
    *(float4*)(&g_zp[lq][b * H + h4]) = o;
}

// ---------------------------------------------------------------------------
// K5: z = sum of 4 partials. 64 blocks x 256 threads, float4 per thread.
// ---------------------------------------------------------------------------
__global__ void k5_combine(float* __restrict__ z) {
    const int i4 = (blockIdx.x * 256 + threadIdx.x) * 4;
    float4 a = *(const float4*)&g_zp[0][i4];
    float4 b = *(const float4*)&g_zp[1][i4];
    float4 c = *(const float4*)&g_zp[2][i4];
    float4 d = *(const float4*)&g_zp[3][i4];
    float4 o = {a.x + b.x + c.x + d.x, a.y + b.y + c.y + d.y,
                a.z + b.z + c.z + d.z, a.w + b.w + c.w + d.w};
    *(float4*)(z + i4) = o;
}

// ---------------------------------------------------------------------------
extern "C" void kernel_launch(void* const* d_in, const int* in_sizes, int n_in,
                              void* d_out, int out_size) {
    const float* wh   = (const float*)d_in[0];
    const float* pe1  = (const float*)d_in[1];
    const float* pe2  = (const float*)d_in[2];
    const int*   e1e  = (const int*)d_in[3];
    const int*   e2e  = (const int*)d_in[4];
    const float* te   = (const float*)d_in[5];
    const float* Wp   = (const float*)d_in[6];
    const float* We   = (const float*)d_in[7];
    const float* v    = (const float*)d_in[8];
    float* z = (float*)d_out;

    cudaFuncSetAttribute(k3_main, cudaFuncAttributeMaxDynamicSharedMemorySize, K3_DSMEM);

    k_prep<<<NB_PF + NB_WP + NB_ENT, 256>>>(wh, pe1, pe2, Wp, e1e, e2e, te);
    k2_dense_ent<<<dim3(8, 32), 256>>>(We);
    k3_main<<<dim3(2, 128), 256, K3_DSMEM>>>(v);
    k4_softmax_zp<<<dim3(B, 4), 256>>>();
    k5_combine<<<64, 256>>>(z);
}